// round 9
// baseline (speedup 1.0000x reference)
#include <cuda_runtime.h>
#include <cuda_bf16.h>
#include <math.h>
#include <stdint.h>

#define BATCH 8
#define SEQ   2048
#define DIM   512
#define ITERS 12
#define KSPLIT 4

typedef __nv_bfloat16 bf16;

// ---------------- scratch (static device memory; no allocations) --------------
__device__ bf16 g_qhi[(size_t)BATCH * SEQ * DIM];
__device__ bf16 g_qlo[(size_t)BATCH * SEQ * DIM];
__device__ bf16 g_khi[(size_t)BATCH * SEQ * DIM];
__device__ bf16 g_klo[(size_t)BATCH * SEQ * DIM];
__device__ bf16 g_vthi[(size_t)BATCH * DIM * SEQ];  // V transposed [b][d][s]
__device__ bf16 g_vtlo[(size_t)BATCH * DIM * SEQ];
__device__ bf16 g_phi[(size_t)BATCH * SEQ * SEQ];   // scores -> probs (hi)
__device__ bf16 g_plo[(size_t)BATCH * SEQ * SEQ];   // scores -> probs (lo)
__device__ float g_part[KSPLIT][(size_t)BATCH * SEQ * DIM];  // pv partials
__device__ float g_w[SEQ];
__device__ float g_blend;
__device__ float g_meanV[BATCH * DIM];
__device__ float g_pa[4096];
__device__ float g_pb[4096];

// ---------------- helpers ----------------------------------------------------
__device__ __forceinline__ uint32_t smem_u32(const void* p) {
    uint32_t a;
    asm("{ .reg .u64 t; cvta.to.shared.u64 t, %1; cvt.u32.u64 %0, t; }" : "=r"(a) : "l"(p));
    return a;
}
__device__ __forceinline__ uint32_t pkbf2(float lo, float hi) {
    uint32_t r;
    asm("cvt.rn.bf16x2.f32 %0, %1, %2;" : "=r"(r) : "f"(hi), "f"(lo));
    return r;
}
__device__ __forceinline__ float bfr(float x) {
    return __bfloat162float(__float2bfloat16_rn(x));
}
__device__ __forceinline__ void hmma16816(float c[4], const uint32_t a[4], const uint32_t b[2]) {
    asm volatile(
        "mma.sync.aligned.m16n8k16.row.col.f32.bf16.bf16.f32 "
        "{%0,%1,%2,%3}, {%4,%5,%6,%7}, {%8,%9}, {%0,%1,%2,%3};"
        : "+f"(c[0]), "+f"(c[1]), "+f"(c[2]), "+f"(c[3])
        : "r"(a[0]), "r"(a[1]), "r"(a[2]), "r"(a[3]), "r"(b[0]), "r"(b[1]));
}
__device__ __forceinline__ void ldsm_x4(uint32_t r[4], uint32_t addr) {
    asm volatile("ldmatrix.sync.aligned.m8n8.x4.shared.b16 {%0,%1,%2,%3}, [%4];"
                 : "=r"(r[0]), "=r"(r[1]), "=r"(r[2]), "=r"(r[3]) : "r"(addr));
}
#define CP_ASYNC16(saddr, gptr) \
    asm volatile("cp.async.cg.shared.global [%0], [%1], 16;" :: "r"(saddr), "l"(gptr))
#define CP_COMMIT() asm volatile("cp.async.commit_group;" ::: "memory")
#define CP_WAIT(n)  asm volatile("cp.async.wait_group %0;" :: "n"(n) : "memory")

__device__ __forceinline__ float wredmax(float v) {
    #pragma unroll
    for (int o = 16; o > 0; o >>= 1) v = fmaxf(v, __shfl_xor_sync(0xffffffffu, v, o));
    return v;
}
__device__ __forceinline__ float wredmin(float v) {
    #pragma unroll
    for (int o = 16; o > 0; o >>= 1) v = fminf(v, __shfl_xor_sync(0xffffffffu, v, o));
    return v;
}
__device__ __forceinline__ float wredsum(float v) {
    #pragma unroll
    for (int o = 16; o > 0; o >>= 1) v += __shfl_xor_sync(0xffffffffu, v, o);
    return v;
}

// ---------------- prep: dragon pattern + softplus weights + blend scalar ------
__global__ void prep_kernel(const float* __restrict__ ps, const float* __restrict__ pb,
                            const float* __restrict__ w1, const float* __restrict__ b1,
                            const float* __restrict__ w2, const float* __restrict__ b2) {
    const int tid = threadIdx.x, nt = blockDim.x;
    const int lane = tid & 31, wid = tid >> 5;
    __shared__ float redmn[32], redmx[32];
    __shared__ float s_mn, s_mx;
    const int it = 11;

    float* cur = g_pa;
    float* tmp = g_pb;
    if (tid == 0) cur[0] = 0.5f;
    __syncthreads();

    int len = 1;
    const float k3 = 1.0f / 3.0f;
    for (int iter = 1; iter < ITERS; ++iter) {
        const int nl = 2 * len + 1;
        for (int j = tid; j < nl; j += nt) {
            float val;
            if (j < len)       val = cur[j];
            else if (j == len) val = 0.5f;
            else               val = 1.0f - cur[nl - 1 - j];
            tmp[j] = val;
        }
        __syncthreads();
        float lmn = 3.4e38f, lmx = -3.4e38f;
        for (int j = tid; j < nl; j += nt) {
            float l = (j > 0)      ? tmp[j - 1] : 0.0f;
            float c = tmp[j];
            float r = (j + 1 < nl) ? tmp[j + 1] : 0.0f;
            float val = l * k3 + c * k3 + r * k3;
            cur[j] = val;
            lmn = fminf(lmn, val);
            lmx = fmaxf(lmx, val);
        }
        lmn = wredmin(lmn);
        lmx = wredmax(lmx);
        if (lane == 0) { redmn[wid] = lmn; redmx[wid] = lmx; }
        __syncthreads();
        if (wid == 0) {
            float a = (lane < nt / 32) ? redmn[lane] : 3.4e38f;
            float c = (lane < nt / 32) ? redmx[lane] : -3.4e38f;
            a = wredmin(a);
            c = wredmax(c);
            if (lane == 0) { s_mn = a; s_mx = c; }
        }
        __syncthreads();
        const float mn = s_mn, mx = s_mx;
        for (int j = tid; j < nl; j += nt)
            cur[j] = (cur[j] - mn) / (mx - mn + 1e-8f);
        __syncthreads();
        len = nl;
    }

    const float sc = ps[it], bi = pb[it];
    for (int s = tid; s < SEQ; s += nt) {
        double x = (double)s / (double)(SEQ - 1);
        double t = x * (double)(len - 1);
        int i0 = (int)t;
        if (i0 > len - 2) i0 = len - 2;
        double fr = t - (double)i0;
        float w = (float)((1.0 - fr) * (double)cur[i0] + fr * (double)cur[i0 + 1]);
        float z = fmaf(w, sc, bi);
        g_w[s] = fmaxf(z, 0.0f) + log1pf(expf(-fabsf(z)));
    }

    if (tid == 0) {
        float acc = b2[0];
        for (int j = 0; j < 64; ++j) {
            float h = w1[it * 64 + j] + b1[j];
            if (h > 0.0f) acc = fmaf(h, w2[j], acc);
        }
        g_blend = 1.0f / (1.0f + expf(-acc));
    }
}

// ---------------- column mean of V per batch -----------------------------------
__global__ void meanv_kernel(const float* __restrict__ V) {
    const int b = blockIdx.y;
    const int d = (blockIdx.x << 7) + threadIdx.x;
    const float* p = V + (size_t)b * SEQ * DIM + d;
    float a0 = 0.f, a1 = 0.f, a2 = 0.f, a3 = 0.f;
    #pragma unroll 4
    for (int k = 0; k < SEQ; k += 4) {
        a0 += p[(size_t)(k + 0) * DIM];
        a1 += p[(size_t)(k + 1) * DIM];
        a2 += p[(size_t)(k + 2) * DIM];
        a3 += p[(size_t)(k + 3) * DIM];
    }
    g_meanV[b * DIM + d] = (a0 + a1 + a2 + a3) * (1.0f / SEQ);
}

// ---------------- split Q/K into bf16 hi/lo -------------------------------------
__global__ __launch_bounds__(256) void splitqk_kernel(const float* __restrict__ Q,
                                                      const float* __restrict__ K) {
    const size_t i = (size_t)blockIdx.x * 256 + threadIdx.x;
    const float* src = (blockIdx.y == 0) ? Q : K;
    bf16* dh = (blockIdx.y == 0) ? g_qhi : g_khi;
    bf16* dl = (blockIdx.y == 0) ? g_qlo : g_klo;
    float4 v = ((const float4*)src)[i];
    float h0 = bfr(v.x), h1 = bfr(v.y), h2 = bfr(v.z), h3 = bfr(v.w);
    uint2 hh = make_uint2(pkbf2(h0, h1), pkbf2(h2, h3));
    uint2 ll = make_uint2(pkbf2(v.x - h0, v.y - h1), pkbf2(v.z - h2, v.w - h3));
    ((uint2*)dh)[i] = hh;
    ((uint2*)dl)[i] = ll;
}

// ---------------- split + transpose V: Vt[b][d][s] bf16 hi/lo -------------------
__global__ void splitv_kernel(const float* __restrict__ V) {
    __shared__ float t[32][33];
    const int b = blockIdx.z;
    const int s0 = blockIdx.x << 5, d0 = blockIdx.y << 5;
    const int tx = threadIdx.x, ty = threadIdx.y;
    const float* src = V + ((size_t)b * SEQ + s0) * DIM + d0 + tx;
    #pragma unroll
    for (int i = 0; i < 32; i += 8) t[ty + i][tx] = src[(size_t)(ty + i) * DIM];
    __syncthreads();
    #pragma unroll
    for (int i = 0; i < 32; i += 8) {
        float x = t[tx][ty + i];
        float h = bfr(x);
        size_t o = ((size_t)b * DIM + d0 + ty + i) * SEQ + s0 + tx;
        g_vthi[o] = __float2bfloat16_rn(h);
        g_vtlo[o] = __float2bfloat16_rn(x - h);
    }
}

// =================================================================================
// Fused HMMA GEMM core (R9): CTA tile 128x256, 256 threads, 2x4 warp grid,
// warp tile 64x64, ONE CTA/SM. C = Ahi*Bhi + Ahi*Blo + Alo*Bhi  (bf16 3-term).
// XOR-swizzled unpadded tiles (rows x 64B; 16B chunk c -> c ^ ((row>>1)&3)),
// 3-stage cp.async pipeline, one __syncthreads per 32-K chunk.
// Fragment buffer xf[] is shared between Alo and Blo terms to cap registers.
// =================================================================================
#define A_TILE_B 8192u               // 128 rows x 64 B
#define B_TILE_B 16384u              // 256 rows x 64 B
#define STAGE_B  (2u * A_TILE_B + 2u * B_TILE_B)   // 49152
#define DSMEM_BYTES (3u * STAGE_B)                 // 147456

#define ISSUE_CHUNK(bufbase, kb) do { \
    _Pragma("unroll") \
    for (int i = 0; i < 2; ++i) { \
        CP_ASYNC16((bufbase) + stA[i], aHi + gA[i] + (kb)); \
        CP_ASYNC16((bufbase) + A_TILE_B + stA[i], aLo + gA[i] + (kb)); \
    } \
    _Pragma("unroll") \
    for (int i = 0; i < 4; ++i) { \
        CP_ASYNC16((bufbase) + 2u * A_TILE_B + stB[i], bHi + gB[i] + (kb)); \
        CP_ASYNC16((bufbase) + 2u * A_TILE_B + B_TILE_B + stB[i], bLo + gB[i] + (kb)); \
    } \
    CP_COMMIT(); \
} while (0)

template <int LDA, int LDB, int CPS>
__device__ __forceinline__ void hmma_fused_mainloop(
    const bf16* aHi, const bf16* aLo, const bf16* bHi, const bf16* bLo,
    bf16* smem, float c[4][8][4])
{
    const int tid = threadIdx.x;
    const int wid = tid >> 5, lane = tid & 31;
    const int wm = wid & 1, wn = wid >> 1;

    const uint32_t smem_base = smem_u32(smem);

    // cp.async store offsets (swizzled): A: 512 16B-chunks, B: 1024 16B-chunks
    uint32_t stA[2], stB[4];
    size_t gA[2], gB[4];
    #pragma unroll
    for (int i = 0; i < 2; ++i) {
        const int idx = i * 256 + tid;
        const int r = idx >> 2, cc = idx & 3;
        stA[i] = (uint32_t)(r * 64 + ((cc ^ ((r >> 1) & 3)) << 4));
        gA[i] = (size_t)r * LDA + cc * 8;
    }
    #pragma unroll
    for (int i = 0; i < 4; ++i) {
        const int idx = i * 256 + tid;
        const int r = idx >> 2, cc = idx & 3;
        stB[i] = (uint32_t)(r * 64 + ((cc ^ ((r >> 1) & 3)) << 4));
        gB[i] = (size_t)r * LDB + cc * 8;
    }

    // ldmatrix lane bases. XOR value invariant across mt/ntp (stride 16 rows).
    const int a_row = wm * 64 + (lane & 15);
    const int a_hi  = (lane >> 4) & 1;
    const int xa    = (a_row >> 1) & 3;
    const uint32_t a_base = (uint32_t)(a_row * 64);
    const int b_row = wn * 64 + (lane & 7) + ((lane & 16) ? 8 : 0);
    const int b_hi  = (lane >> 3) & 1;
    const int xb    = (b_row >> 1) & 3;
    const uint32_t b_base = (uint32_t)(b_row * 64);

    // prefetch chunks 0 and 1
    ISSUE_CHUNK(smem_base, 0);
    ISSUE_CHUNK(smem_base + STAGE_B, 32);

    #pragma unroll 1
    for (int ch = 0; ch < CPS; ++ch) {
        if (ch + 1 < CPS) { CP_WAIT(1); } else { CP_WAIT(0); }
        __syncthreads();
        if (ch + 2 < CPS) {
            const uint32_t nb = smem_base + (uint32_t)((ch + 2) % 3) * STAGE_B;
            const int kb = (ch + 2) * 32;
            ISSUE_CHUNK(nb, kb);
        }

        const uint32_t bb = smem_base + (uint32_t)(ch % 3) * STAGE_B;
        #pragma unroll
        for (int ks = 0; ks < 2; ++ks) {
            const uint32_t ka  = (uint32_t)(((ks * 2 + a_hi) ^ xa) << 4);
            const uint32_t kb2 = (uint32_t)(((ks * 2 + b_hi) ^ xb) << 4);
            uint32_t ah[4][4], bh[4][4], xf[4][4];
            #pragma unroll
            for (int mt = 0; mt < 4; ++mt)
                ldsm_x4(ah[mt], bb + a_base + mt * 1024u + ka);
            #pragma unroll
            for (int ntp = 0; ntp < 4; ++ntp)
                ldsm_x4(bh[ntp], bb + 2u * A_TILE_B + b_base + ntp * 1024u + kb2);
            // hi * hi
            #pragma unroll
            for (int mt = 0; mt < 4; ++mt)
                #pragma unroll
                for (int nt = 0; nt < 8; ++nt)
                    hmma16816(c[mt][nt], ah[mt], &bh[nt >> 1][(nt & 1) * 2]);
            // lo * hi  (xf = A-lo fragments)
            #pragma unroll
            for (int mt = 0; mt < 4; ++mt)
                ldsm_x4(xf[mt], bb + A_TILE_B + a_base + mt * 1024u + ka);
            #pragma unroll
            for (int mt = 0; mt < 4; ++mt)
                #pragma unroll
                for (int nt = 0; nt < 8; ++nt)
                    hmma16816(c[mt][nt], xf[mt], &bh[nt >> 1][(nt & 1) * 2]);
            // hi * lo  (xf reused = B-lo fragments)
            #pragma unroll
            for (int ntp = 0; ntp < 4; ++ntp)
                ldsm_x4(xf[ntp], bb + 2u * A_TILE_B + B_TILE_B + b_base + ntp * 1024u + kb2);
            #pragma unroll
            for (int mt = 0; mt < 4; ++mt)
                #pragma unroll
                for (int nt = 0; nt < 8; ++nt)
                    hmma16816(c[mt][nt], ah[mt], &xf[nt >> 1][(nt & 1) * 2]);
        }
    }
}

// ---------------- GEMM1: S = (Q.K^T) * w[n]/sqrt(D) -> bf16 hi/lo ----------------
__global__ __launch_bounds__(256, 1) void scores_mma_kernel() {
    extern __shared__ bf16 dynsmem[];
    __shared__ float s_ws[256];

    const int tid = threadIdx.x, wid = tid >> 5, lane = tid & 31;
    const int grp = lane >> 2, t4 = lane & 3;
    const int wm = wid & 1, wn = wid >> 1;
    const int b = blockIdx.z, m0 = blockIdx.y << 7, n0 = blockIdx.x << 8;

    s_ws[tid] = g_w[n0 + tid] * 0.04419417382415922f;

    const size_t boff = (size_t)b * SEQ * DIM;
    const bf16* A0 = g_qhi + boff + (size_t)m0 * DIM;
    const bf16* A1 = g_qlo + boff + (size_t)m0 * DIM;
    const bf16* B0 = g_khi + boff + (size_t)n0 * DIM;
    const bf16* B1 = g_klo + boff + (size_t)n0 * DIM;

    float c[4][8][4];
    #pragma unroll
    for (int i = 0; i < 4; ++i)
        #pragma unroll
        for (int j = 0; j < 8; ++j)
            #pragma unroll
            for (int q = 0; q < 4; ++q) c[i][j][q] = 0.f;

    hmma_fused_mainloop<DIM, DIM, DIM / 32>(A0, A1, B0, B1, dynsmem, c);

    bf16* phb = g_phi + (size_t)b * SEQ * SEQ;
    bf16* plb = g_plo + (size_t)b * SEQ * SEQ;
    #pragma unroll
    for (int mt = 0; mt < 4; ++mt) {
        #pragma unroll
        for (int nt = 0; nt < 8; ++nt) {
            const int col_l = wn * 64 + nt * 8 + t4 * 2;
            const int col = n0 + col_l;
            const float w0 = s_ws[col_l], w1v = s_ws[col_l + 1];
            #pragma unroll
            for (int rr = 0; rr < 2; ++rr) {
                const int row = m0 + wm * 64 + mt * 16 + grp + rr * 8;
                float x0 = c[mt][nt][2 * rr]     * w0;
                float x1 = c[mt][nt][2 * rr + 1] * w1v;
                float h0 = bfr(x0), h1 = bfr(x1);
                *(uint32_t*)(phb + (size_t)row * SEQ + col) = pkbf2(h0, h1);
                *(uint32_t*)(plb + (size_t)row * SEQ + col) = pkbf2(x0 - h0, x1 - h1);
            }
        }
    }
}

// ---------------- softmax over bf16 hi/lo scores, write probs hi/lo --------------
__global__ __launch_bounds__(256) void softmax_kernel2() {
    const size_t row = blockIdx.x;
    bf16* ph = g_phi + row * SEQ;
    bf16* pl = g_plo + row * SEQ;
    const int tid = threadIdx.x, lane = tid & 31, wid = tid >> 5;
    __shared__ float red[8];

    uint4 uh = ((const uint4*)ph)[tid];
    uint4 ul = ((const uint4*)pl)[tid];
    float x[8];
    const __nv_bfloat162* h2 = (const __nv_bfloat162*)&uh;
    const __nv_bfloat162* l2 = (const __nv_bfloat162*)&ul;
    #pragma unroll
    for (int q = 0; q < 4; ++q) {
        float2 a = __bfloat1622float2(h2[q]);
        float2 c = __bfloat1622float2(l2[q]);
        x[2 * q]     = a.x + c.x;
        x[2 * q + 1] = a.y + c.y;
    }

    float m = x[0];
    #pragma unroll
    for (int i = 1; i < 8; ++i) m = fmaxf(m, x[i]);
    m = wredmax(m);
    if (lane == 0) red[wid] = m;
    __syncthreads();
    m = red[0];
    #pragma unroll
    for (int i = 1; i < 8; ++i) m = fmaxf(m, red[i]);
    __syncthreads();

    float e[8], s = 0.f;
    #pragma unroll
    for (int i = 0; i < 8; ++i) { e[i] = __expf(x[i] - m); s += e[i]; }
    s = wredsum(s);
    if (lane == 0) red[wid] = s;
    __syncthreads();
    float tot = 0.f;
    #pragma unroll
    for (int i = 0; i < 8; ++i) tot += red[i];
    const float inv = 1.0f / tot;

    uint32_t hh[4], ll[4];
    #pragma unroll
    for (int q = 0; q < 4; ++q) {
        float p0 = e[2 * q] * inv, p1 = e[2 * q + 1] * inv;
        float h0 = bfr(p0), h1 = bfr(p1);
        hh[q] = pkbf2(h0, h1);
        ll[q] = pkbf2(p0 - h0, p1 - h1);
    }
    ((uint4*)ph)[tid] = *(uint4*)hh;
    ((uint4*)pl)[tid] = *(uint4*)ll;
}

// ---------------- GEMM2 (K-split): part[s] = P[:, ks] . V[ks, :] ------------------
__global__ __launch_bounds__(256, 1) void pv_mma_kernel() {
    extern __shared__ bf16 dynsmem[];

    const int tid = threadIdx.x, wid = tid >> 5, lane = tid & 31;
    const int grp = lane >> 2, t4 = lane & 3;
    const int wm = wid & 1, wn = wid >> 1;
    const int b = blockIdx.z >> 2, s = blockIdx.z & 3;
    const int m0 = blockIdx.y << 7, n0 = blockIdx.x << 8;
    const int k0 = s * (SEQ / KSPLIT);

    const bf16* A0 = g_phi + (size_t)b * SEQ * SEQ + (size_t)m0 * SEQ + k0;
    const bf16* A1 = g_plo + (size_t)b * SEQ * SEQ + (size_t)m0 * SEQ + k0;
    const bf16* B0 = g_vthi + (size_t)b * DIM * SEQ + (size_t)n0 * SEQ + k0;
    const bf16* B1 = g_vtlo + (size_t)b * DIM * SEQ + (size_t)n0 * SEQ + k0;

    float c[4][8][4];
    #pragma unroll
    for (int i = 0; i < 4; ++i)
        #pragma unroll
        for (int j = 0; j < 8; ++j)
            #pragma unroll
            for (int q = 0; q < 4; ++q) c[i][j][q] = 0.f;

    hmma_fused_mainloop<SEQ, SEQ, (SEQ / KSPLIT) / 32>(A0, A1, B0, B1, dynsmem, c);

    float* pout = g_part[s] + (size_t)b * SEQ * DIM;
    #pragma unroll
    for (int mt = 0; mt < 4; ++mt) {
        #pragma unroll
        for (int nt = 0; nt < 8; ++nt) {
            const int col = n0 + wn * 64 + nt * 8 + t4 * 2;
            #pragma unroll
            for (int rr = 0; rr < 2; ++rr) {
                const int row = m0 + wm * 64 + mt * 16 + grp + rr * 8;
                float2 o = make_float2(c[mt][nt][2 * rr], c[mt][nt][2 * rr + 1]);
                *(float2*)(pout + (size_t)row * DIM + col) = o;
            }
        }
    }
}

// ---------------- reduce: out = blend * sum(parts) + (1-blend) * meanV -----------
__global__ __launch_bounds__(256) void reduce_kernel(float* __restrict__ out) {
    const size_t i4 = (size_t)blockIdx.x * 256 + threadIdx.x;   // float4 index
    const float blend = g_blend;
    const float ob = 1.0f - blend;
    const size_t ei = i4 * 4;
    const int b = (int)(ei / ((size_t)SEQ * DIM));
    const int d = (int)(ei % DIM);

    float4 p0 = ((const float4*)g_part[0])[i4];
    float4 p1 = ((const float4*)g_part[1])[i4];
    float4 p2 = ((const float4*)g_part[2])[i4];
    float4 p3 = ((const float4*)g_part[3])[i4];
    const float* mv = g_meanV + b * DIM + d;

    float4 o;
    o.x = fmaf(blend, (p0.x + p1.x) + (p2.x + p3.x), ob * mv[0]);
    o.y = fmaf(blend, (p0.y + p1.y) + (p2.y + p3.y), ob * mv[1]);
    o.z = fmaf(blend, (p0.z + p1.z) + (p2.z + p3.z), ob * mv[2]);
    o.w = fmaf(blend, (p0.w + p1.w) + (p2.w + p3.w), ob * mv[3]);
    ((float4*)out)[i4] = o;
}

// ---------------- launch -----------------------------------------------------------
extern "C" void kernel_launch(void* const* d_in, const int* in_sizes, int n_in,
                              void* d_out, int out_size) {
    const float* q  = (const float*)d_in[0];
    const float* k  = (const float*)d_in[1];
    const float* v  = (const float*)d_in[2];
    const float* ps = (const float*)d_in[3];
    const float* pb = (const float*)d_in[4];
    const float* w1 = (const float*)d_in[5];
    const float* b1 = (const float*)d_in[6];
    const float* w2 = (const float*)d_in[7];
    const float* b2 = (const float*)d_in[8];
    float* out = (float*)d_out;

    static bool attr_set = false;
    if (!attr_set) {
        cudaFuncSetAttribute(scores_mma_kernel,
                             cudaFuncAttributeMaxDynamicSharedMemorySize, DSMEM_BYTES);
        cudaFuncSetAttribute(pv_mma_kernel,
                             cudaFuncAttributeMaxDynamicSharedMemorySize, DSMEM_BYTES);
        attr_set = true;
    }

    prep_kernel<<<1, 1024>>>(ps, pb, w1, b1, w2, b2);
    splitqk_kernel<<<dim3((BATCH * SEQ * DIM / 4) / 256, 2), 256>>>(q, k);
    splitv_kernel<<<dim3(SEQ / 32, DIM / 32, BATCH), dim3(32, 8)>>>(v);
    scores_mma_kernel<<<dim3(SEQ / 256, SEQ / 128, BATCH), 256, DSMEM_BYTES>>>();
    meanv_kernel<<<dim3(DIM / 128, BATCH), 128>>>(v);
    softmax_kernel2<<<BATCH * SEQ, 256>>>();
    pv_mma_kernel<<<dim3(DIM / 256, SEQ / 128, BATCH * KSPLIT), 256, DSMEM_BYTES>>>();
    reduce_kernel<<<(BATCH * SEQ * DIM / 4) / 256, 256>>>(out);
}

// round 10
// speedup vs baseline: 1.1881x; 1.1881x over previous
#include <cuda_runtime.h>
#include <cuda_bf16.h>
#include <cuda_fp16.h>
#include <math.h>
#include <stdint.h>

#define BATCH 8
#define SEQ   2048
#define DIM   512
#define ITERS 12
#define KSPLIT 4

typedef __nv_bfloat16 bf16;

// ---------------- scratch (static device memory; no allocations) --------------
__device__ bf16 g_qhi[(size_t)BATCH * SEQ * DIM];
__device__ bf16 g_qlo[(size_t)BATCH * SEQ * DIM];
__device__ bf16 g_khi[(size_t)BATCH * SEQ * DIM];
__device__ bf16 g_klo[(size_t)BATCH * SEQ * DIM];
__device__ __half g_vthi[(size_t)BATCH * DIM * SEQ];  // V^T fp16 hi
__device__ __half g_vtlo[(size_t)BATCH * DIM * SEQ];  // V^T fp16 lo
__device__ bf16 g_phi[(size_t)BATCH * SEQ * SEQ];     // scores hi (bf16)
__device__ bf16 g_plo[(size_t)BATCH * SEQ * SEQ];     // scores lo (bf16)
__device__ __half g_p16[(size_t)BATCH * SEQ * SEQ];   // probs (fp16, single)
__device__ float g_part[KSPLIT][(size_t)BATCH * SEQ * DIM];  // pv partials
__device__ float g_w[SEQ];
__device__ float g_blend;
__device__ float g_meanV[BATCH * DIM];
__device__ float g_pa[4096];
__device__ float g_pb[4096];

// ---------------- helpers ----------------------------------------------------
__device__ __forceinline__ uint32_t smem_u32(const void* p) {
    uint32_t a;
    asm("{ .reg .u64 t; cvta.to.shared.u64 t, %1; cvt.u32.u64 %0, t; }" : "=r"(a) : "l"(p));
    return a;
}
__device__ __forceinline__ uint32_t pkbf2(float lo, float hi) {
    uint32_t r;
    asm("cvt.rn.bf16x2.f32 %0, %1, %2;" : "=r"(r) : "f"(hi), "f"(lo));
    return r;
}
__device__ __forceinline__ float bfr(float x) {
    return __bfloat162float(__float2bfloat16_rn(x));
}
__device__ __forceinline__ void hmma16816(float c[4], const uint32_t a[4], const uint32_t b[2]) {
    asm volatile(
        "mma.sync.aligned.m16n8k16.row.col.f32.bf16.bf16.f32 "
        "{%0,%1,%2,%3}, {%4,%5,%6,%7}, {%8,%9}, {%0,%1,%2,%3};"
        : "+f"(c[0]), "+f"(c[1]), "+f"(c[2]), "+f"(c[3])
        : "r"(a[0]), "r"(a[1]), "r"(a[2]), "r"(a[3]), "r"(b[0]), "r"(b[1]));
}
__device__ __forceinline__ void hmma16816f(float c[4], const uint32_t a[4], const uint32_t b[2]) {
    asm volatile(
        "mma.sync.aligned.m16n8k16.row.col.f32.f16.f16.f32 "
        "{%0,%1,%2,%3}, {%4,%5,%6,%7}, {%8,%9}, {%0,%1,%2,%3};"
        : "+f"(c[0]), "+f"(c[1]), "+f"(c[2]), "+f"(c[3])
        : "r"(a[0]), "r"(a[1]), "r"(a[2]), "r"(a[3]), "r"(b[0]), "r"(b[1]));
}
__device__ __forceinline__ void ldsm_x4(uint32_t r[4], uint32_t addr) {
    asm volatile("ldmatrix.sync.aligned.m8n8.x4.shared.b16 {%0,%1,%2,%3}, [%4];"
                 : "=r"(r[0]), "=r"(r[1]), "=r"(r[2]), "=r"(r[3]) : "r"(addr));
}
#define CP_ASYNC16(saddr, gptr) \
    asm volatile("cp.async.cg.shared.global [%0], [%1], 16;" :: "r"(saddr), "l"(gptr))
#define CP_COMMIT() asm volatile("cp.async.commit_group;" ::: "memory")
#define CP_WAIT(n)  asm volatile("cp.async.wait_group %0;" :: "n"(n) : "memory")

__device__ __forceinline__ float wredmax(float v) {
    #pragma unroll
    for (int o = 16; o > 0; o >>= 1) v = fmaxf(v, __shfl_xor_sync(0xffffffffu, v, o));
    return v;
}
__device__ __forceinline__ float wredmin(float v) {
    #pragma unroll
    for (int o = 16; o > 0; o >>= 1) v = fminf(v, __shfl_xor_sync(0xffffffffu, v, o));
    return v;
}
__device__ __forceinline__ float wredsum(float v) {
    #pragma unroll
    for (int o = 16; o > 0; o >>= 1) v += __shfl_xor_sync(0xffffffffu, v, o);
    return v;
}

// ---------------- prep: dragon pattern + softplus weights + blend scalar ------
__global__ void prep_kernel(const float* __restrict__ ps, const float* __restrict__ pb,
                            const float* __restrict__ w1, const float* __restrict__ b1,
                            const float* __restrict__ w2, const float* __restrict__ b2) {
    const int tid = threadIdx.x, nt = blockDim.x;
    const int lane = tid & 31, wid = tid >> 5;
    __shared__ float redmn[32], redmx[32];
    __shared__ float s_mn, s_mx;
    const int it = 11;

    float* cur = g_pa;
    float* tmp = g_pb;
    if (tid == 0) cur[0] = 0.5f;
    __syncthreads();

    int len = 1;
    const float k3 = 1.0f / 3.0f;
    for (int iter = 1; iter < ITERS; ++iter) {
        const int nl = 2 * len + 1;
        for (int j = tid; j < nl; j += nt) {
            float val;
            if (j < len)       val = cur[j];
            else if (j == len) val = 0.5f;
            else               val = 1.0f - cur[nl - 1 - j];
            tmp[j] = val;
        }
        __syncthreads();
        float lmn = 3.4e38f, lmx = -3.4e38f;
        for (int j = tid; j < nl; j += nt) {
            float l = (j > 0)      ? tmp[j - 1] : 0.0f;
            float c = tmp[j];
            float r = (j + 1 < nl) ? tmp[j + 1] : 0.0f;
            float val = l * k3 + c * k3 + r * k3;
            cur[j] = val;
            lmn = fminf(lmn, val);
            lmx = fmaxf(lmx, val);
        }
        lmn = wredmin(lmn);
        lmx = wredmax(lmx);
        if (lane == 0) { redmn[wid] = lmn; redmx[wid] = lmx; }
        __syncthreads();
        if (wid == 0) {
            float a = (lane < nt / 32) ? redmn[lane] : 3.4e38f;
            float c = (lane < nt / 32) ? redmx[lane] : -3.4e38f;
            a = wredmin(a);
            c = wredmax(c);
            if (lane == 0) { s_mn = a; s_mx = c; }
        }
        __syncthreads();
        const float mn = s_mn, mx = s_mx;
        for (int j = tid; j < nl; j += nt)
            cur[j] = (cur[j] - mn) / (mx - mn + 1e-8f);
        __syncthreads();
        len = nl;
    }

    const float sc = ps[it], bi = pb[it];
    for (int s = tid; s < SEQ; s += nt) {
        double x = (double)s / (double)(SEQ - 1);
        double t = x * (double)(len - 1);
        int i0 = (int)t;
        if (i0 > len - 2) i0 = len - 2;
        double fr = t - (double)i0;
        float w = (float)((1.0 - fr) * (double)cur[i0] + fr * (double)cur[i0 + 1]);
        float z = fmaf(w, sc, bi);
        g_w[s] = fmaxf(z, 0.0f) + log1pf(expf(-fabsf(z)));
    }

    if (tid == 0) {
        float acc = b2[0];
        for (int j = 0; j < 64; ++j) {
            float h = w1[it * 64 + j] + b1[j];
            if (h > 0.0f) acc = fmaf(h, w2[j], acc);
        }
        g_blend = 1.0f / (1.0f + expf(-acc));
    }
}

// ---------------- column mean of V per batch -----------------------------------
__global__ void meanv_kernel(const float* __restrict__ V) {
    const int b = blockIdx.y;
    const int d = (blockIdx.x << 7) + threadIdx.x;
    const float* p = V + (size_t)b * SEQ * DIM + d;
    float a0 = 0.f, a1 = 0.f, a2 = 0.f, a3 = 0.f;
    #pragma unroll 4
    for (int k = 0; k < SEQ; k += 4) {
        a0 += p[(size_t)(k + 0) * DIM];
        a1 += p[(size_t)(k + 1) * DIM];
        a2 += p[(size_t)(k + 2) * DIM];
        a3 += p[(size_t)(k + 3) * DIM];
    }
    g_meanV[b * DIM + d] = (a0 + a1 + a2 + a3) * (1.0f / SEQ);
}

// ---------------- split Q/K into bf16 hi/lo -------------------------------------
__global__ __launch_bounds__(256) void splitqk_kernel(const float* __restrict__ Q,
                                                      const float* __restrict__ K) {
    const size_t i = (size_t)blockIdx.x * 256 + threadIdx.x;
    const float* src = (blockIdx.y == 0) ? Q : K;
    bf16* dh = (blockIdx.y == 0) ? g_qhi : g_khi;
    bf16* dl = (blockIdx.y == 0) ? g_qlo : g_klo;
    float4 v = ((const float4*)src)[i];
    float h0 = bfr(v.x), h1 = bfr(v.y), h2 = bfr(v.z), h3 = bfr(v.w);
    uint2 hh = make_uint2(pkbf2(h0, h1), pkbf2(h2, h3));
    uint2 ll = make_uint2(pkbf2(v.x - h0, v.y - h1), pkbf2(v.z - h2, v.w - h3));
    ((uint2*)dh)[i] = hh;
    ((uint2*)dl)[i] = ll;
}

// ---------------- split + transpose V: Vt[b][d][s] fp16 hi/lo -------------------
__global__ void splitv_kernel(const float* __restrict__ V) {
    __shared__ float t[32][33];
    const int b = blockIdx.z;
    const int s0 = blockIdx.x << 5, d0 = blockIdx.y << 5;
    const int tx = threadIdx.x, ty = threadIdx.y;
    const float* src = V + ((size_t)b * SEQ + s0) * DIM + d0 + tx;
    #pragma unroll
    for (int i = 0; i < 32; i += 8) t[ty + i][tx] = src[(size_t)(ty + i) * DIM];
    __syncthreads();
    #pragma unroll
    for (int i = 0; i < 32; i += 8) {
        float x = t[tx][ty + i];
        __half h = __float2half_rn(x);
        size_t o = ((size_t)b * DIM + d0 + ty + i) * SEQ + s0 + tx;
        g_vthi[o] = h;
        g_vtlo[o] = __float2half_rn(x - __half2float(h));
    }
}

// =================================================================================
// Scores GEMM core (R8 config): 256 threads, 2x4 warp grid, warp tile 64x32.
// C[128x128] = Ahi*Bhi + Ahi*Blo + Alo*Bhi  (bf16 3-term)
// XOR-swizzled unpadded tiles (128 rows x 64B; 16B chunk c -> c ^ ((row>>1)&3)),
// 3-stage cp.async pipeline, ONE __syncthreads per 32-K chunk.
// =================================================================================
#define TILE_B 8192u                 // bytes per 128x32 16-bit tile
#define BUF_B  (4u * TILE_B)         // 4 tiles per stage (32 KB)
#define DSMEM_BYTES (3u * BUF_B)     // 3 stages (96 KB)

#define ISSUE_CHUNK(bufbase, kb) do { \
    CP_ASYNC16((bufbase) + 0u * TILE_B + st0, aHi + g0a + (kb)); \
    CP_ASYNC16((bufbase) + 0u * TILE_B + st1, aHi + g1a + (kb)); \
    CP_ASYNC16((bufbase) + 1u * TILE_B + st0, aLo + g0a + (kb)); \
    CP_ASYNC16((bufbase) + 1u * TILE_B + st1, aLo + g1a + (kb)); \
    CP_ASYNC16((bufbase) + 2u * TILE_B + st0, bHi + g0b + (kb)); \
    CP_ASYNC16((bufbase) + 2u * TILE_B + st1, bHi + g1b + (kb)); \
    CP_ASYNC16((bufbase) + 3u * TILE_B + st0, bLo + g0b + (kb)); \
    CP_ASYNC16((bufbase) + 3u * TILE_B + st1, bLo + g1b + (kb)); \
    CP_COMMIT(); \
} while (0)

template <int LDA, int LDB, int CPS>
__device__ __forceinline__ void hmma_fused_mainloop(
    const bf16* aHi, const bf16* aLo, const bf16* bHi, const bf16* bLo,
    bf16* smem, float c[4][4][4])
{
    const int tid = threadIdx.x;
    const int wid = tid >> 5, lane = tid & 31;
    const int wm = wid & 1, wn = wid >> 1;

    const uint32_t smem_base = smem_u32(smem);

    const int r0 = tid >> 2,         c0 = tid & 3;
    const int r1 = (256 + tid) >> 2, c1 = tid & 3;
    const uint32_t st0 = (uint32_t)(r0 * 64 + ((c0 ^ ((r0 >> 1) & 3)) << 4));
    const uint32_t st1 = (uint32_t)(r1 * 64 + ((c1 ^ ((r1 >> 1) & 3)) << 4));
    const size_t g0a = (size_t)r0 * LDA + c0 * 8, g1a = (size_t)r1 * LDA + c1 * 8;
    const size_t g0b = (size_t)r0 * LDB + c0 * 8, g1b = (size_t)r1 * LDB + c1 * 8;

    const int a_row = wm * 64 + (lane & 15);
    const int a_hi  = (lane >> 4) & 1;
    const int xa    = (a_row >> 1) & 3;
    const uint32_t a_base = (uint32_t)(a_row * 64);
    const int b_row = wn * 32 + (lane & 7) + ((lane & 16) ? 8 : 0);
    const int b_hi  = (lane >> 3) & 1;
    const int xb    = (b_row >> 1) & 3;
    const uint32_t b_base = (uint32_t)(b_row * 64);

    ISSUE_CHUNK(smem_base, 0);
    ISSUE_CHUNK(smem_base + BUF_B, 32);

    #pragma unroll 1
    for (int ch = 0; ch < CPS; ++ch) {
        if (ch + 1 < CPS) { CP_WAIT(1); } else { CP_WAIT(0); }
        __syncthreads();
        if (ch + 2 < CPS) {
            const uint32_t nb = smem_base + (uint32_t)((ch + 2) % 3) * BUF_B;
            const int kb = (ch + 2) * 32;
            ISSUE_CHUNK(nb, kb);
        }

        const uint32_t bb = smem_base + (uint32_t)(ch % 3) * BUF_B;
        #pragma unroll
        for (int ks = 0; ks < 2; ++ks) {
            const uint32_t ka  = (uint32_t)(((ks * 2 + a_hi) ^ xa) << 4);
            const uint32_t kb2 = (uint32_t)(((ks * 2 + b_hi) ^ xb) << 4);
            uint32_t ah[4][4], bh[2][4];
            #pragma unroll
            for (int mt = 0; mt < 4; ++mt)
                ldsm_x4(ah[mt], bb + 0u * TILE_B + a_base + mt * 1024u + ka);
            #pragma unroll
            for (int ntp = 0; ntp < 2; ++ntp)
                ldsm_x4(bh[ntp], bb + 2u * TILE_B + b_base + ntp * 1024u + kb2);
            #pragma unroll
            for (int mt = 0; mt < 4; ++mt)
                #pragma unroll
                for (int nt = 0; nt < 4; ++nt)
                    hmma16816(c[mt][nt], ah[mt], &bh[nt >> 1][(nt & 1) * 2]);
            {
                uint32_t al[4][4];
                #pragma unroll
                for (int mt = 0; mt < 4; ++mt)
                    ldsm_x4(al[mt], bb + 1u * TILE_B + a_base + mt * 1024u + ka);
                #pragma unroll
                for (int mt = 0; mt < 4; ++mt)
                    #pragma unroll
                    for (int nt = 0; nt < 4; ++nt)
                        hmma16816(c[mt][nt], al[mt], &bh[nt >> 1][(nt & 1) * 2]);
            }
            {
                uint32_t bl[2][4];
                #pragma unroll
                for (int ntp = 0; ntp < 2; ++ntp)
                    ldsm_x4(bl[ntp], bb + 3u * TILE_B + b_base + ntp * 1024u + kb2);
                #pragma unroll
                for (int mt = 0; mt < 4; ++mt)
                    #pragma unroll
                    for (int nt = 0; nt < 4; ++nt)
                        hmma16816(c[mt][nt], ah[mt], &bl[nt >> 1][(nt & 1) * 2]);
            }
        }
    }
}

// ---------------- GEMM1: S = (Q.K^T) * w[n]/sqrt(D) -> bf16 hi/lo ----------------
__global__ __launch_bounds__(256, 2) void scores_mma_kernel() {
    extern __shared__ bf16 dynsmem[];
    __shared__ float s_ws[128];

    const int tid = threadIdx.x, wid = tid >> 5, lane = tid & 31;
    const int grp = lane >> 2, t4 = lane & 3;
    const int wm = wid & 1, wn = wid >> 1;
    const int b = blockIdx.z, m0 = blockIdx.y << 7, n0 = blockIdx.x << 7;

    if (tid < 128) s_ws[tid] = g_w[n0 + tid] * 0.04419417382415922f;

    const size_t boff = (size_t)b * SEQ * DIM;
    const bf16* A0 = g_qhi + boff + (size_t)m0 * DIM;
    const bf16* A1 = g_qlo + boff + (size_t)m0 * DIM;
    const bf16* B0 = g_khi + boff + (size_t)n0 * DIM;
    const bf16* B1 = g_klo + boff + (size_t)n0 * DIM;

    float c[4][4][4];
    #pragma unroll
    for (int i = 0; i < 4; ++i)
        #pragma unroll
        for (int j = 0; j < 4; ++j)
            #pragma unroll
            for (int q = 0; q < 4; ++q) c[i][j][q] = 0.f;

    hmma_fused_mainloop<DIM, DIM, DIM / 32>(A0, A1, B0, B1, dynsmem, c);

    bf16* phb = g_phi + (size_t)b * SEQ * SEQ;
    bf16* plb = g_plo + (size_t)b * SEQ * SEQ;
    #pragma unroll
    for (int mt = 0; mt < 4; ++mt) {
        #pragma unroll
        for (int nt = 0; nt < 4; ++nt) {
            const int col_l = wn * 32 + nt * 8 + t4 * 2;
            const int col = n0 + col_l;
            const float w0 = s_ws[col_l], w1v = s_ws[col_l + 1];
            #pragma unroll
            for (int rr = 0; rr < 2; ++rr) {
                const int row = m0 + wm * 64 + mt * 16 + grp + rr * 8;
                float x0 = c[mt][nt][2 * rr]     * w0;
                float x1 = c[mt][nt][2 * rr + 1] * w1v;
                float h0 = bfr(x0), h1 = bfr(x1);
                *(uint32_t*)(phb + (size_t)row * SEQ + col) = pkbf2(h0, h1);
                *(uint32_t*)(plb + (size_t)row * SEQ + col) = pkbf2(x0 - h0, x1 - h1);
            }
        }
    }
}

// ---------------- softmax over bf16 hi/lo scores, write fp16 probs ----------------
__global__ __launch_bounds__(256) void softmax_kernel2() {
    const size_t row = blockIdx.x;
    const bf16* ph = g_phi + row * SEQ;
    const bf16* pl = g_plo + row * SEQ;
    __half* po = g_p16 + row * SEQ;
    const int tid = threadIdx.x, lane = tid & 31, wid = tid >> 5;
    __shared__ float red[8];

    uint4 uh = ((const uint4*)ph)[tid];
    uint4 ul = ((const uint4*)pl)[tid];
    float x[8];
    const __nv_bfloat162* h2 = (const __nv_bfloat162*)&uh;
    const __nv_bfloat162* l2 = (const __nv_bfloat162*)&ul;
    #pragma unroll
    for (int q = 0; q < 4; ++q) {
        float2 a = __bfloat1622float2(h2[q]);
        float2 c = __bfloat1622float2(l2[q]);
        x[2 * q]     = a.x + c.x;
        x[2 * q + 1] = a.y + c.y;
    }

    float m = x[0];
    #pragma unroll
    for (int i = 1; i < 8; ++i) m = fmaxf(m, x[i]);
    m = wredmax(m);
    if (lane == 0) red[wid] = m;
    __syncthreads();
    m = red[0];
    #pragma unroll
    for (int i = 1; i < 8; ++i) m = fmaxf(m, red[i]);
    __syncthreads();

    float e[8], s = 0.f;
    #pragma unroll
    for (int i = 0; i < 8; ++i) { e[i] = __expf(x[i] - m); s += e[i]; }
    s = wredsum(s);
    if (lane == 0) red[wid] = s;
    __syncthreads();
    float tot = 0.f;
    #pragma unroll
    for (int i = 0; i < 8; ++i) tot += red[i];
    const float inv = 1.0f / tot;

    __half2 hh[4];
    #pragma unroll
    for (int q = 0; q < 4; ++q)
        hh[q] = __floats2half2_rn(e[2 * q] * inv, e[2 * q + 1] * inv);
    ((uint4*)po)[tid] = *(uint4*)hh;
}

// =================================================================================
// PV GEMM core: 2-term fp16. C[128x128] = P*Vhi + P*Vlo.
// Same warp layout as scores; stage = A + Bhi + Blo = 24 KB; 3 stages.
// =================================================================================
#define PV_STAGE_B (3u * TILE_B)        // 24576
#define PV_DSMEM   (3u * PV_STAGE_B)    // 73728

#define PV_ISSUE_CHUNK(bufbase, kb) do { \
    CP_ASYNC16((bufbase) + 0u * TILE_B + st0, aP + g0a + (kb)); \
    CP_ASYNC16((bufbase) + 0u * TILE_B + st1, aP + g1a + (kb)); \
    CP_ASYNC16((bufbase) + 1u * TILE_B + st0, bHi + g0b + (kb)); \
    CP_ASYNC16((bufbase) + 1u * TILE_B + st1, bHi + g1b + (kb)); \
    CP_ASYNC16((bufbase) + 2u * TILE_B + st0, bLo + g0b + (kb)); \
    CP_ASYNC16((bufbase) + 2u * TILE_B + st1, bLo + g1b + (kb)); \
    CP_COMMIT(); \
} while (0)

template <int LDA, int LDB, int CPS>
__device__ __forceinline__ void pv_mainloop(
    const __half* aP, const __half* bHi, const __half* bLo,
    __half* smem, float c[4][4][4])
{
    const int tid = threadIdx.x;
    const int wid = tid >> 5, lane = tid & 31;
    const int wm = wid & 1, wn = wid >> 1;

    const uint32_t smem_base = smem_u32(smem);

    const int r0 = tid >> 2,         c0 = tid & 3;
    const int r1 = (256 + tid) >> 2, c1 = tid & 3;
    const uint32_t st0 = (uint32_t)(r0 * 64 + ((c0 ^ ((r0 >> 1) & 3)) << 4));
    const uint32_t st1 = (uint32_t)(r1 * 64 + ((c1 ^ ((r1 >> 1) & 3)) << 4));
    const size_t g0a = (size_t)r0 * LDA + c0 * 8, g1a = (size_t)r1 * LDA + c1 * 8;
    const size_t g0b = (size_t)r0 * LDB + c0 * 8, g1b = (size_t)r1 * LDB + c1 * 8;

    const int a_row = wm * 64 + (lane & 15);
    const int a_hi  = (lane >> 4) & 1;
    const int xa    = (a_row >> 1) & 3;
    const uint32_t a_base = (uint32_t)(a_row * 64);
    const int b_row = wn * 32 + (lane & 7) + ((lane & 16) ? 8 : 0);
    const int b_hi  = (lane >> 3) & 1;
    const int xb    = (b_row >> 1) & 3;
    const uint32_t b_base = (uint32_t)(b_row * 64);

    PV_ISSUE_CHUNK(smem_base, 0);
    PV_ISSUE_CHUNK(smem_base + PV_STAGE_B, 32);

    #pragma unroll 1
    for (int ch = 0; ch < CPS; ++ch) {
        if (ch + 1 < CPS) { CP_WAIT(1); } else { CP_WAIT(0); }
        __syncthreads();
        if (ch + 2 < CPS) {
            const uint32_t nb = smem_base + (uint32_t)((ch + 2) % 3) * PV_STAGE_B;
            const int kb = (ch + 2) * 32;
            PV_ISSUE_CHUNK(nb, kb);
        }

        const uint32_t bb = smem_base + (uint32_t)(ch % 3) * PV_STAGE_B;
        #pragma unroll
        for (int ks = 0; ks < 2; ++ks) {
            const uint32_t ka  = (uint32_t)(((ks * 2 + a_hi) ^ xa) << 4);
            const uint32_t kb2 = (uint32_t)(((ks * 2 + b_hi) ^ xb) << 4);
            uint32_t ah[4][4], bh[2][4];
            #pragma unroll
            for (int mt = 0; mt < 4; ++mt)
                ldsm_x4(ah[mt], bb + 0u * TILE_B + a_base + mt * 1024u + ka);
            #pragma unroll
            for (int ntp = 0; ntp < 2; ++ntp)
                ldsm_x4(bh[ntp], bb + 1u * TILE_B + b_base + ntp * 1024u + kb2);
            #pragma unroll
            for (int mt = 0; mt < 4; ++mt)
                #pragma unroll
                for (int nt = 0; nt < 4; ++nt)
                    hmma16816f(c[mt][nt], ah[mt], &bh[nt >> 1][(nt & 1) * 2]);
            {
                uint32_t bl[2][4];
                #pragma unroll
                for (int ntp = 0; ntp < 2; ++ntp)
                    ldsm_x4(bl[ntp], bb + 2u * TILE_B + b_base + ntp * 1024u + kb2);
                #pragma unroll
                for (int mt = 0; mt < 4; ++mt)
                    #pragma unroll
                    for (int nt = 0; nt < 4; ++nt)
                        hmma16816f(c[mt][nt], ah[mt], &bl[nt >> 1][(nt & 1) * 2]);
            }
        }
    }
}

// ---------------- GEMM2 (K-split): part[s] = P[:, ks] . V[ks, :] ------------------
__global__ __launch_bounds__(256, 2) void pv_mma_kernel() {
    extern __shared__ __half dynsmem_h[];

    const int tid = threadIdx.x, wid = tid >> 5, lane = tid & 31;
    const int grp = lane >> 2, t4 = lane & 3;
    const int wm = wid & 1, wn = wid >> 1;
    const int b = blockIdx.z >> 2, s = blockIdx.z & 3;
    const int m0 = blockIdx.y << 7, n0 = blockIdx.x << 7;
    const int k0 = s * (SEQ / KSPLIT);

    const __half* A0 = g_p16 + (size_t)b * SEQ * SEQ + (size_t)m0 * SEQ + k0;
    const __half* B0 = g_vthi + (size_t)b * DIM * SEQ + (size_t)n0 * SEQ + k0;
    const __half* B1 = g_vtlo + (size_t)b * DIM * SEQ + (size_t)n0 * SEQ + k0;

    float c[4][4][4];
    #pragma unroll
    for (int i = 0; i < 4; ++i)
        #pragma unroll
        for (int j = 0; j < 4; ++j)
            #pragma unroll
            for (int q = 0; q < 4; ++q) c[i][j][q] = 0.f;

    pv_mainloop<SEQ, SEQ, (SEQ / KSPLIT) / 32>(A0, B0, B1, dynsmem_h, c);

    float* pout = g_part[s] + (size_t)b * SEQ * DIM;
    #pragma unroll
    for (int mt = 0; mt < 4; ++mt) {
        #pragma unroll
        for (int nt = 0; nt < 4; ++nt) {
            const int col = n0 + wn * 32 + nt * 8 + t4 * 2;
            #pragma unroll
            for (int rr = 0; rr < 2; ++rr) {
                const int row = m0 + wm * 64 + mt * 16 + grp + rr * 8;
                float2 o = make_float2(c[mt][nt][2 * rr], c[mt][nt][2 * rr + 1]);
                *(float2*)(pout + (size_t)row * DIM + col) = o;
            }
        }
    }
}

// ---------------- reduce: out = blend * sum(parts) + (1-blend) * meanV -----------
__global__ __launch_bounds__(256) void reduce_kernel(float* __restrict__ out) {
    const size_t i4 = (size_t)blockIdx.x * 256 + threadIdx.x;   // float4 index
    const float blend = g_blend;
    const float ob = 1.0f - blend;
    const size_t ei = i4 * 4;
    const int b = (int)(ei / ((size_t)SEQ * DIM));
    const int d = (int)(ei % DIM);

    float4 p0 = ((const float4*)g_part[0])[i4];
    float4 p1 = ((const float4*)g_part[1])[i4];
    float4 p2 = ((const float4*)g_part[2])[i4];
    float4 p3 = ((const float4*)g_part[3])[i4];
    const float* mv = g_meanV + b * DIM + d;

    float4 o;
    o.x = fmaf(blend, (p0.x + p1.x) + (p2.x + p3.x), ob * mv[0]);
    o.y = fmaf(blend, (p0.y + p1.y) + (p2.y + p3.y), ob * mv[1]);
    o.z = fmaf(blend, (p0.z + p1.z) + (p2.z + p3.z), ob * mv[2]);
    o.w = fmaf(blend, (p0.w + p1.w) + (p2.w + p3.w), ob * mv[3]);
    ((float4*)out)[i4] = o;
}

// ---------------- launch -----------------------------------------------------------
extern "C" void kernel_launch(void* const* d_in, const int* in_sizes, int n_in,
                              void* d_out, int out_size) {
    const float* q  = (const float*)d_in[0];
    const float* k  = (const float*)d_in[1];
    const float* v  = (const float*)d_in[2];
    const float* ps = (const float*)d_in[3];
    const float* pb = (const float*)d_in[4];
    const float* w1 = (const float*)d_in[5];
    const float* b1 = (const float*)d_in[6];
    const float* w2 = (const float*)d_in[7];
    const float* b2 = (const float*)d_in[8];
    float* out = (float*)d_out;

    static bool attr_set = false;
    if (!attr_set) {
        cudaFuncSetAttribute(scores_mma_kernel,
                             cudaFuncAttributeMaxDynamicSharedMemorySize, DSMEM_BYTES);
        cudaFuncSetAttribute(pv_mma_kernel,
                             cudaFuncAttributeMaxDynamicSharedMemorySize, PV_DSMEM);
        attr_set = true;
    }

    prep_kernel<<<1, 1024>>>(ps, pb, w1, b1, w2, b2);
    splitqk_kernel<<<dim3((BATCH * SEQ * DIM / 4) / 256, 2), 256>>>(q, k);
    splitv_kernel<<<dim3(SEQ / 32, DIM / 32, BATCH), dim3(32, 8)>>>(v);
    scores_mma_kernel<<<dim3(SEQ / 128, SEQ / 128, BATCH), 256, DSMEM_BYTES>>>();
    meanv_kernel<<<dim3(DIM / 128, BATCH), 128>>>(v);
    softmax_kernel2<<<BATCH * SEQ, 256>>>();
    pv_mma_kernel<<<dim3(DIM / 128, SEQ / 128, BATCH * KSPLIT), 256, PV_DSMEM>>>();
    reduce_kernel<<<(BATCH * SEQ * DIM / 4) / 256, 256>>>(out);
}

// round 12
// speedup vs baseline: 1.5157x; 1.2757x over previous
#include <cuda_runtime.h>
#include <cuda_bf16.h>
#include <cuda_fp16.h>
#include <math.h>
#include <stdint.h>

#define BATCH 8
#define SEQ   2048
#define DIM   512
#define ITERS 12
#define KSPLIT 4

typedef __nv_bfloat16 bf16;

// ---------------- scratch (static device memory; no allocations) --------------
__device__ __half g_qhi[(size_t)BATCH * SEQ * DIM];   // Q fp16 hi
__device__ __half g_qlo[(size_t)BATCH * SEQ * DIM];   // Q fp16 lo
__device__ __half g_k16[(size_t)BATCH * SEQ * DIM];   // K fp16 single
__device__ __half g_vt16[(size_t)BATCH * DIM * SEQ];  // V^T fp16 single
__device__ bf16 g_phi[(size_t)BATCH * SEQ * SEQ];     // scores hi (bf16)
__device__ bf16 g_plo[(size_t)BATCH * SEQ * SEQ];     // scores lo (bf16)
__device__ __half g_p16[(size_t)BATCH * SEQ * SEQ];   // probs (fp16, single)
__device__ float g_part[KSPLIT][(size_t)BATCH * SEQ * DIM];  // pv partials
__device__ float g_w[SEQ];
__device__ float g_blend;
__device__ float g_meanV[BATCH * DIM];
__device__ float g_pa[4096];
__device__ float g_pb[4096];

// ---------------- helpers ----------------------------------------------------
__device__ __forceinline__ uint32_t smem_u32(const void* p) {
    uint32_t a;
    asm("{ .reg .u64 t; cvta.to.shared.u64 t, %1; cvt.u32.u64 %0, t; }" : "=r"(a) : "l"(p));
    return a;
}
__device__ __forceinline__ uint32_t pkbf2(float lo, float hi) {
    uint32_t r;
    asm("cvt.rn.bf16x2.f32 %0, %1, %2;" : "=r"(r) : "f"(hi), "f"(lo));
    return r;
}
__device__ __forceinline__ float bfr(float x) {
    return __bfloat162float(__float2bfloat16_rn(x));
}
__device__ __forceinline__ void hmma16816f(float c[4], const uint32_t a[4], const uint32_t b[2]) {
    asm volatile(
        "mma.sync.aligned.m16n8k16.row.col.f32.f16.f16.f32 "
        "{%0,%1,%2,%3}, {%4,%5,%6,%7}, {%8,%9}, {%0,%1,%2,%3};"
        : "+f"(c[0]), "+f"(c[1]), "+f"(c[2]), "+f"(c[3])
        : "r"(a[0]), "r"(a[1]), "r"(a[2]), "r"(a[3]), "r"(b[0]), "r"(b[1]));
}
__device__ __forceinline__ void ldsm_x4(uint32_t r[4], uint32_t addr) {
    asm volatile("ldmatrix.sync.aligned.m8n8.x4.shared.b16 {%0,%1,%2,%3}, [%4];"
                 : "=r"(r[0]), "=r"(r[1]), "=r"(r[2]), "=r"(r[3]) : "r"(addr));
}
#define CP_ASYNC16(saddr, gptr) \
    asm volatile("cp.async.cg.shared.global [%0], [%1], 16;" :: "r"(saddr), "l"(gptr))
#define CP_COMMIT() asm volatile("cp.async.commit_group;" ::: "memory")
#define CP_WAIT(n)  asm volatile("cp.async.wait_group %0;" :: "n"(n) : "memory")

__device__ __forceinline__ float wredmax(float v) {
    #pragma unroll
    for (int o = 16; o > 0; o >>= 1) v = fmaxf(v, __shfl_xor_sync(0xffffffffu, v, o));
    return v;
}
__device__ __forceinline__ float wredmin(float v) {
    #pragma unroll
    for (int o = 16; o > 0; o >>= 1) v = fminf(v, __shfl_xor_sync(0xffffffffu, v, o));
    return v;
}
__device__ __forceinline__ float wredsum(float v) {
    #pragma unroll
    for (int o = 16; o > 0; o >>= 1) v += __shfl_xor_sync(0xffffffffu, v, o);
    return v;
}

// ---------------- prep: dragon pattern + softplus weights + blend scalar ------
__global__ void prep_kernel(const float* __restrict__ ps, const float* __restrict__ pb,
                            const float* __restrict__ w1, const float* __restrict__ b1,
                            const float* __restrict__ w2, const float* __restrict__ b2) {
    const int tid = threadIdx.x, nt = blockDim.x;
    const int lane = tid & 31, wid = tid >> 5;
    __shared__ float redmn[32], redmx[32];
    __shared__ float s_mn, s_mx;
    const int it = 11;

    float* cur = g_pa;
    float* tmp = g_pb;
    if (tid == 0) cur[0] = 0.5f;
    __syncthreads();

    int len = 1;
    const float k3 = 1.0f / 3.0f;
    for (int iter = 1; iter < ITERS; ++iter) {
        const int nl = 2 * len + 1;
        for (int j = tid; j < nl; j += nt) {
            float val;
            if (j < len)       val = cur[j];
            else if (j == len) val = 0.5f;
            else               val = 1.0f - cur[nl - 1 - j];
            tmp[j] = val;
        }
        __syncthreads();
        float lmn = 3.4e38f, lmx = -3.4e38f;
        for (int j = tid; j < nl; j += nt) {
            float l = (j > 0)      ? tmp[j - 1] : 0.0f;
            float c = tmp[j];
            float r = (j + 1 < nl) ? tmp[j + 1] : 0.0f;
            float val = l * k3 + c * k3 + r * k3;
            cur[j] = val;
            lmn = fminf(lmn, val);
            lmx = fmaxf(lmx, val);
        }
        lmn = wredmin(lmn);
        lmx = wredmax(lmx);
        if (lane == 0) { redmn[wid] = lmn; redmx[wid] = lmx; }
        __syncthreads();
        if (wid == 0) {
            float a = (lane < nt / 32) ? redmn[lane] : 3.4e38f;
            float c = (lane < nt / 32) ? redmx[lane] : -3.4e38f;
            a = wredmin(a);
            c = wredmax(c);
            if (lane == 0) { s_mn = a; s_mx = c; }
        }
        __syncthreads();
        const float mn = s_mn, mx = s_mx;
        for (int j = tid; j < nl; j += nt)
            cur[j] = (cur[j] - mn) / (mx - mn + 1e-8f);
        __syncthreads();
        len = nl;
    }

    const float sc = ps[it], bi = pb[it];
    for (int s = tid; s < SEQ; s += nt) {
        double x = (double)s / (double)(SEQ - 1);
        double t = x * (double)(len - 1);
        int i0 = (int)t;
        if (i0 > len - 2) i0 = len - 2;
        double fr = t - (double)i0;
        float w = (float)((1.0 - fr) * (double)cur[i0] + fr * (double)cur[i0 + 1]);
        float z = fmaf(w, sc, bi);
        g_w[s] = fmaxf(z, 0.0f) + log1pf(expf(-fabsf(z)));
    }

    if (tid == 0) {
        float acc = b2[0];
        for (int j = 0; j < 64; ++j) {
            float h = w1[it * 64 + j] + b1[j];
            if (h > 0.0f) acc = fmaf(h, w2[j], acc);
        }
        g_blend = 1.0f / (1.0f + expf(-acc));
    }
}

// ---------------- column mean of V per batch -----------------------------------
__global__ void meanv_kernel(const float* __restrict__ V) {
    const int b = blockIdx.y;
    const int d = (blockIdx.x << 7) + threadIdx.x;
    const float* p = V + (size_t)b * SEQ * DIM + d;
    float a0 = 0.f, a1 = 0.f, a2 = 0.f, a3 = 0.f;
    #pragma unroll 4
    for (int k = 0; k < SEQ; k += 4) {
        a0 += p[(size_t)(k + 0) * DIM];
        a1 += p[(size_t)(k + 1) * DIM];
        a2 += p[(size_t)(k + 2) * DIM];
        a3 += p[(size_t)(k + 3) * DIM];
    }
    g_meanV[b * DIM + d] = (a0 + a1 + a2 + a3) * (1.0f / SEQ);
}

// ---------------- split Q (fp16 hi/lo) and K (fp16 single) -----------------------
__global__ __launch_bounds__(256) void splitqk_kernel(const float* __restrict__ Q,
                                                      const float* __restrict__ K) {
    const size_t i = (size_t)blockIdx.x * 256 + threadIdx.x;
    if (blockIdx.y == 0) {
        float4 v = ((const float4*)Q)[i];
        __half h0 = __float2half_rn(v.x), h1 = __float2half_rn(v.y);
        __half h2 = __float2half_rn(v.z), h3 = __float2half_rn(v.w);
        __half2 hh[2] = {__halves2half2(h0, h1), __halves2half2(h2, h3)};
        __half2 ll[2] = {
            __floats2half2_rn(v.x - __half2float(h0), v.y - __half2float(h1)),
            __floats2half2_rn(v.z - __half2float(h2), v.w - __half2float(h3))};
        ((uint2*)g_qhi)[i] = *(uint2*)hh;
        ((uint2*)g_qlo)[i] = *(uint2*)ll;
    } else {
        float4 v = ((const float4*)K)[i];
        __half2 kk[2] = {__floats2half2_rn(v.x, v.y), __floats2half2_rn(v.z, v.w)};
        ((uint2*)g_k16)[i] = *(uint2*)kk;
    }
}

// ---------------- transpose V: Vt[b][d][s] fp16 single ---------------------------
__global__ void splitv_kernel(const float* __restrict__ V) {
    __shared__ float t[32][33];
    const int b = blockIdx.z;
    const int s0 = blockIdx.x << 5, d0 = blockIdx.y << 5;
    const int tx = threadIdx.x, ty = threadIdx.y;
    const float* src = V + ((size_t)b * SEQ + s0) * DIM + d0 + tx;
    #pragma unroll
    for (int i = 0; i < 32; i += 8) t[ty + i][tx] = src[(size_t)(ty + i) * DIM];
    __syncthreads();
    #pragma unroll
    for (int i = 0; i < 32; i += 8) {
        float x = t[tx][ty + i];
        size_t o = ((size_t)b * DIM + d0 + ty + i) * SEQ + s0 + tx;
        g_vt16[o] = __float2half_rn(x);
    }
}

#define TILE_B 8192u                 // bytes per 128x32 16-bit tile

// =================================================================================
// Scores GEMM core: 2-term fp16. C[128x128] = Qhi*K + Qlo*K.
// 256 threads, 2x4 warp grid, warp tile 64x32. XOR-swizzled 64B rows.
// Stage = [Ahi, Alo, B] = 24 KB; 3 stages; one barrier per 32-K chunk.
// =================================================================================
#define SC_STAGE_B (3u * TILE_B)        // 24576
#define SC_DSMEM   (3u * SC_STAGE_B)    // 73728

#define SC_ISSUE_CHUNK(bufbase, kb) do { \
    CP_ASYNC16((bufbase) + 0u * TILE_B + st0, aHi + g0a + (kb)); \
    CP_ASYNC16((bufbase) + 0u * TILE_B + st1, aHi + g1a + (kb)); \
    CP_ASYNC16((bufbase) + 1u * TILE_B + st0, aLo + g0a + (kb)); \
    CP_ASYNC16((bufbase) + 1u * TILE_B + st1, aLo + g1a + (kb)); \
    CP_ASYNC16((bufbase) + 2u * TILE_B + st0, bK + g0b + (kb)); \
    CP_ASYNC16((bufbase) + 2u * TILE_B + st1, bK + g1b + (kb)); \
    CP_COMMIT(); \
} while (0)

template <int LDA, int LDB, int CPS>
__device__ __forceinline__ void scores_mainloop(
    const __half* aHi, const __half* aLo, const __half* bK,
    __half* smem, float c[4][4][4])
{
    const int tid = threadIdx.x;
    const int wid = tid >> 5, lane = tid & 31;
    const int wm = wid & 1, wn = wid >> 1;

    const uint32_t smem_base = smem_u32(smem);

    const int r0 = tid >> 2,         c0 = tid & 3;
    const int r1 = (256 + tid) >> 2, c1 = tid & 3;
    const uint32_t st0 = (uint32_t)(r0 * 64 + ((c0 ^ ((r0 >> 1) & 3)) << 4));
    const uint32_t st1 = (uint32_t)(r1 * 64 + ((c1 ^ ((r1 >> 1) & 3)) << 4));
    const size_t g0a = (size_t)r0 * LDA + c0 * 8, g1a = (size_t)r1 * LDA + c1 * 8;
    const size_t g0b = (size_t)r0 * LDB + c0 * 8, g1b = (size_t)r1 * LDB + c1 * 8;

    const int a_row = wm * 64 + (lane & 15);
    const int a_hi  = (lane >> 4) & 1;
    const int xa    = (a_row >> 1) & 3;
    const uint32_t a_base = (uint32_t)(a_row * 64);
    const int b_row = wn * 32 + (lane & 7) + ((lane & 16) ? 8 : 0);
    const int b_hi  = (lane >> 3) & 1;
    const int xb    = (b_row >> 1) & 3;
    const uint32_t b_base = (uint32_t)(b_row * 64);

    SC_ISSUE_CHUNK(smem_base, 0);
    SC_ISSUE_CHUNK(smem_base + SC_STAGE_B, 32);

    #pragma unroll 1
    for (int ch = 0; ch < CPS; ++ch) {
        if (ch + 1 < CPS) { CP_WAIT(1); } else { CP_WAIT(0); }
        __syncthreads();
        if (ch + 2 < CPS) {
            const uint32_t nb = smem_base + (uint32_t)((ch + 2) % 3) * SC_STAGE_B;
            const int kb = (ch + 2) * 32;
            SC_ISSUE_CHUNK(nb, kb);
        }

        const uint32_t bb = smem_base + (uint32_t)(ch % 3) * SC_STAGE_B;
        #pragma unroll
        for (int ks = 0; ks < 2; ++ks) {
            const uint32_t ka  = (uint32_t)(((ks * 2 + a_hi) ^ xa) << 4);
            const uint32_t kb2 = (uint32_t)(((ks * 2 + b_hi) ^ xb) << 4);
            uint32_t ah[4][4], bh[2][4];
            #pragma unroll
            for (int mt = 0; mt < 4; ++mt)
                ldsm_x4(ah[mt], bb + 0u * TILE_B + a_base + mt * 1024u + ka);
            #pragma unroll
            for (int ntp = 0; ntp < 2; ++ntp)
                ldsm_x4(bh[ntp], bb + 2u * TILE_B + b_base + ntp * 1024u + kb2);
            #pragma unroll
            for (int mt = 0; mt < 4; ++mt)
                #pragma unroll
                for (int nt = 0; nt < 4; ++nt)
                    hmma16816f(c[mt][nt], ah[mt], &bh[nt >> 1][(nt & 1) * 2]);
            {
                uint32_t al[4][4];
                #pragma unroll
                for (int mt = 0; mt < 4; ++mt)
                    ldsm_x4(al[mt], bb + 1u * TILE_B + a_base + mt * 1024u + ka);
                #pragma unroll
                for (int mt = 0; mt < 4; ++mt)
                    #pragma unroll
                    for (int nt = 0; nt < 4; ++nt)
                        hmma16816f(c[mt][nt], al[mt], &bh[nt >> 1][(nt & 1) * 2]);
            }
        }
    }
}

// ---------------- GEMM1: S = (Q.K^T) * w[n]/sqrt(D) -> bf16 hi/lo ----------------
__global__ __launch_bounds__(256, 2) void scores_mma_kernel() {
    extern __shared__ __half dynsmem_h[];
    __shared__ float s_ws[128];

    const int tid = threadIdx.x, wid = tid >> 5, lane = tid & 31;
    const int grp = lane >> 2, t4 = lane & 3;
    const int wm = wid & 1, wn = wid >> 1;
    const int b = blockIdx.z, m0 = blockIdx.y << 7, n0 = blockIdx.x << 7;

    if (tid < 128) s_ws[tid] = g_w[n0 + tid] * 0.04419417382415922f;

    const size_t boff = (size_t)b * SEQ * DIM;
    const __half* A0 = g_qhi + boff + (size_t)m0 * DIM;
    const __half* A1 = g_qlo + boff + (size_t)m0 * DIM;
    const __half* B0 = g_k16 + boff + (size_t)n0 * DIM;

    float c[4][4][4];
    #pragma unroll
    for (int i = 0; i < 4; ++i)
        #pragma unroll
        for (int j = 0; j < 4; ++j)
            #pragma unroll
            for (int q = 0; q < 4; ++q) c[i][j][q] = 0.f;

    scores_mainloop<DIM, DIM, DIM / 32>(A0, A1, B0, dynsmem_h, c);

    bf16* phb = g_phi + (size_t)b * SEQ * SEQ;
    bf16* plb = g_plo + (size_t)b * SEQ * SEQ;
    #pragma unroll
    for (int mt = 0; mt < 4; ++mt) {
        #pragma unroll
        for (int nt = 0; nt < 4; ++nt) {
            const int col_l = wn * 32 + nt * 8 + t4 * 2;
            const int col = n0 + col_l;
            const float w0 = s_ws[col_l], w1v = s_ws[col_l + 1];
            #pragma unroll
            for (int rr = 0; rr < 2; ++rr) {
                const int row = m0 + wm * 64 + mt * 16 + grp + rr * 8;
                float x0 = c[mt][nt][2 * rr]     * w0;
                float x1 = c[mt][nt][2 * rr + 1] * w1v;
                float h0 = bfr(x0), h1 = bfr(x1);
                *(uint32_t*)(phb + (size_t)row * SEQ + col) = pkbf2(h0, h1);
                *(uint32_t*)(plb + (size_t)row * SEQ + col) = pkbf2(x0 - h0, x1 - h1);
            }
        }
    }
}

// ---------------- softmax over bf16 hi/lo scores, write fp16 probs ----------------
__global__ __launch_bounds__(256) void softmax_kernel2() {
    const size_t row = blockIdx.x;
    const bf16* ph = g_phi + row * SEQ;
    const bf16* pl = g_plo + row * SEQ;
    __half* po = g_p16 + row * SEQ;
    const int tid = threadIdx.x, lane = tid & 31, wid = tid >> 5;
    __shared__ float red[8];

    uint4 uh = ((const uint4*)ph)[tid];
    uint4 ul = ((const uint4*)pl)[tid];
    float x[8];
    const __nv_bfloat162* h2 = (const __nv_bfloat162*)&uh;
    const __nv_bfloat162* l2 = (const __nv_bfloat162*)&ul;
    #pragma unroll
    for (int q = 0; q < 4; ++q) {
        float2 a = __bfloat1622float2(h2[q]);
        float2 c = __bfloat1622float2(l2[q]);
        x[2 * q]     = a.x + c.x;
        x[2 * q + 1] = a.y + c.y;
    }

    float m = x[0];
    #pragma unroll
    for (int i = 1; i < 8; ++i) m = fmaxf(m, x[i]);
    m = wredmax(m);
    if (lane == 0) red[wid] = m;
    __syncthreads();
    m = red[0];
    #pragma unroll
    for (int i = 1; i < 8; ++i) m = fmaxf(m, red[i]);
    __syncthreads();

    float e[8], s = 0.f;
    #pragma unroll
    for (int i = 0; i < 8; ++i) { e[i] = __expf(x[i] - m); s += e[i]; }
    s = wredsum(s);
    if (lane == 0) red[wid] = s;
    __syncthreads();
    float tot = 0.f;
    #pragma unroll
    for (int i = 0; i < 8; ++i) tot += red[i];
    const float inv = 1.0f / tot;

    __half2 hh[4];
    #pragma unroll
    for (int q = 0; q < 4; ++q)
        hh[q] = __floats2half2_rn(e[2 * q] * inv, e[2 * q + 1] * inv);
    ((uint4*)po)[tid] = *(uint4*)hh;
}

// =================================================================================
// PV GEMM core: 1-term fp16, K-chunk 64 (two 32-sub-tiles per stage).
// Stage = [A_k0, A_k1, B_k0, B_k1] = 32 KB; 3 stages.
// =================================================================================
#define PV_STAGE_B (4u * TILE_B)        // 32768
#define PV_DSMEM   (3u * PV_STAGE_B)    // 98304

#define PV_ISSUE_CHUNK(bufbase, kb) do { \
    CP_ASYNC16((bufbase) + 0u * TILE_B + st0, aP + g0a + (kb)); \
    CP_ASYNC16((bufbase) + 0u * TILE_B + st1, aP + g1a + (kb)); \
    CP_ASYNC16((bufbase) + 1u * TILE_B + st0, aP + g0a + (kb) + 32); \
    CP_ASYNC16((bufbase) + 1u * TILE_B + st1, aP + g1a + (kb) + 32); \
    CP_ASYNC16((bufbase) + 2u * TILE_B + st0, bV + g0b + (kb)); \
    CP_ASYNC16((bufbase) + 2u * TILE_B + st1, bV + g1b + (kb)); \
    CP_ASYNC16((bufbase) + 3u * TILE_B + st0, bV + g0b + (kb) + 32); \
    CP_ASYNC16((bufbase) + 3u * TILE_B + st1, bV + g1b + (kb) + 32); \
    CP_COMMIT(); \
} while (0)

template <int LDA, int LDB, int CPS>   // CPS = number of 64-K chunks
__device__ __forceinline__ void pv_mainloop(
    const __half* aP, const __half* bV,
    __half* smem, float c[4][4][4])
{
    const int tid = threadIdx.x;
    const int wid = tid >> 5, lane = tid & 31;
    const int wm = wid & 1, wn = wid >> 1;

    const uint32_t smem_base = smem_u32(smem);

    const int r0 = tid >> 2,         c0 = tid & 3;
    const int r1 = (256 + tid) >> 2, c1 = tid & 3;
    const uint32_t st0 = (uint32_t)(r0 * 64 + ((c0 ^ ((r0 >> 1) & 3)) << 4));
    const uint32_t st1 = (uint32_t)(r1 * 64 + ((c1 ^ ((r1 >> 1) & 3)) << 4));
    const size_t g0a = (size_t)r0 * LDA + c0 * 8, g1a = (size_t)r1 * LDA + c1 * 8;
    const size_t g0b = (size_t)r0 * LDB + c0 * 8, g1b = (size_t)r1 * LDB + c1 * 8;

    const int a_row = wm * 64 + (lane & 15);
    const int a_hi  = (lane >> 4) & 1;
    const int xa    = (a_row >> 1) & 3;
    const uint32_t a_base = (uint32_t)(a_row * 64);
    const int b_row = wn * 32 + (lane & 7) + ((lane & 16) ? 8 : 0);
    const int b_hi  = (lane >> 3) & 1;
    const int xb    = (b_row >> 1) & 3;
    const uint32_t b_base = (uint32_t)(b_row * 64);

    PV_ISSUE_CHUNK(smem_base, 0);
    PV_ISSUE_CHUNK(smem_base + PV_STAGE_B, 64);

    #pragma unroll 1
    for (int ch = 0; ch < CPS; ++ch) {
        if (ch + 1 < CPS) { CP_WAIT(1); } else { CP_WAIT(0); }
        __syncthreads();
        if (ch + 2 < CPS) {
            const uint32_t nb = smem_base + (uint32_t)((ch + 2) % 3) * PV_STAGE_B;
            const int kb = (ch + 2) * 64;
            PV_ISSUE_CHUNK(nb, kb);
        }

        const uint32_t bb = smem_base + (uint32_t)(ch % 3) * PV_STAGE_B;
        #pragma unroll
        for (int sub = 0; sub < 2; ++sub) {
            #pragma unroll
            for (int ks = 0; ks < 2; ++ks) {
                const uint32_t ka  = (uint32_t)(((ks * 2 + a_hi) ^ xa) << 4);
                const uint32_t kb2 = (uint32_t)(((ks * 2 + b_hi) ^ xb) << 4);
                uint32_t ah[4][4], bh[2][4];
                #pragma unroll
                for (int mt = 0; mt < 4; ++mt)
                    ldsm_x4(ah[mt], bb + (uint32_t)sub * TILE_B + a_base + mt * 1024u + ka);
                #pragma unroll
                for (int ntp = 0; ntp < 2; ++ntp)
                    ldsm_x4(bh[ntp], bb + (2u + sub) * TILE_B + b_base + ntp * 1024u + kb2);
                #pragma unroll
                for (int mt = 0; mt < 4; ++mt)
                    #pragma unroll
                    for (int nt = 0; nt < 4; ++nt)
                        hmma16816f(c[mt][nt], ah[mt], &bh[nt >> 1][(nt & 1) * 2]);
            }
        }
    }
}

// ---------------- GEMM2 (K-split): part[s] = P[:, ks] . V[ks, :] ------------------
__global__ __launch_bounds__(256, 2) void pv_mma_kernel() {
    extern __shared__ __half dynsmem_h[];

    const int tid = threadIdx.x, wid = tid >> 5, lane = tid & 31;
    const int grp = lane >> 2, t4 = lane & 3;
    const int wm = wid & 1, wn = wid >> 1;
    const int b = blockIdx.z >> 2, s = blockIdx.z & 3;
    const int m0 = blockIdx.y << 7, n0 = blockIdx.x << 7;
    const int k0 = s * (SEQ / KSPLIT);

    const __half* A0 = g_p16 + (size_t)b * SEQ * SEQ + (size_t)m0 * SEQ + k0;
    const __half* B0 = g_vt16 + (size_t)b * DIM * SEQ + (size_t)n0 * SEQ + k0;

    float c[4][4][4];
    #pragma unroll
    for (int i = 0; i < 4; ++i)
        #pragma unroll
        for (int j = 0; j < 4; ++j)
            #pragma unroll
            for (int q = 0; q < 4; ++q) c[i][j][q] = 0.f;

    pv_mainloop<SEQ, SEQ, (SEQ / KSPLIT) / 64>(A0, B0, dynsmem_h, c);

    float* pout = g_part[s] + (size_t)b * SEQ * DIM;
    #pragma unroll
    for (int mt = 0; mt < 4; ++mt) {
        #pragma unroll
        for (int nt = 0; nt < 4; ++nt) {
            const int col = n0 + wn * 32 + nt * 8 + t4 * 2;
            #pragma unroll
            for (int rr = 0; rr < 2; ++rr) {
                const int row = m0 + wm * 64 + mt * 16 + grp + rr * 8;
                float2 o = make_float2(c[mt][nt][2 * rr], c[mt][nt][2 * rr + 1]);
                *(float2*)(pout + (size_t)row * DIM + col) = o;
            }
        }
    }
}

// ---------------- reduce: out = blend * sum(parts) + (1-blend) * meanV -----------
__global__ __launch_bounds__(256) void reduce_kernel(float* __restrict__ out) {
    const size_t i4 = (size_t)blockIdx.x * 256 + threadIdx.x;   // float4 index
    const float blend = g_blend;
    const float ob = 1.0f - blend;
    const size_t ei = i4 * 4;
    const int b = (int)(ei / ((size_t)SEQ * DIM));
    const int d = (int)(ei % DIM);

    float4 p0 = ((const float4*)g_part[0])[i4];
    float4 p1 = ((const float4*)g_part[1])[i4];
    float4 p2 = ((const float4*)g_part[2])[i4];
    float4 p3 = ((const float4*)g_part[3])[i4];
    const float* mv = g_meanV + b * DIM + d;

    float4 o;
    o.x = fmaf(blend, (p0.x + p1.x) + (p2.x + p3.x), ob * mv[0]);
    o.y = fmaf(blend, (p0.y + p1.y) + (p2.y + p3.y), ob * mv[1]);
    o.z = fmaf(blend, (p0.z + p1.z) + (p2.z + p3.z), ob * mv[2]);
    o.w = fmaf(blend, (p0.w + p1.w) + (p2.w + p3.w), ob * mv[3]);
    ((float4*)out)[i4] = o;
}

// ---------------- launch -----------------------------------------------------------
extern "C" void kernel_launch(void* const* d_in, const int* in_sizes, int n_in,
                              void* d_out, int out_size) {
    const float* q  = (const float*)d_in[0];
    const float* k  = (const float*)d_in[1];
    const float* v  = (const float*)d_in[2];
    const float* ps = (const float*)d_in[3];
    const float* pb = (const float*)d_in[4];
    const float* w1 = (const float*)d_in[5];
    const float* b1 = (const float*)d_in[6];
    const float* w2 = (const float*)d_in[7];
    const float* b2 = (const float*)d_in[8];
    float* out = (float*)d_out;

    static bool attr_set = false;
    if (!attr_set) {
        cudaFuncSetAttribute(scores_mma_kernel,
                             cudaFuncAttributeMaxDynamicSharedMemorySize, SC_DSMEM);
        cudaFuncSetAttribute(pv_mma_kernel,
                             cudaFuncAttributeMaxDynamicSharedMemorySize, PV_DSMEM);
        attr_set = true;
    }

    prep_kernel<<<1, 1024>>>(ps, pb, w1, b1, w2, b2);
    splitqk_kernel<<<dim3((BATCH * SEQ * DIM / 4) / 256, 2), 256>>>(q, k);
    splitv_kernel<<<dim3(SEQ / 32, DIM / 32, BATCH), dim3(32, 8)>>>(v);
    scores_mma_kernel<<<dim3(SEQ / 128, SEQ / 128, BATCH), 256, SC_DSMEM>>>();
    meanv_kernel<<<dim3(DIM / 128, BATCH), 128>>>(v);
    softmax_kernel2<<<BATCH * SEQ, 256>>>();
    pv_mma_kernel<<<dim3(DIM / 128, SEQ / 128, BATCH * KSPLIT), 256, PV_DSMEM>>>();
    reduce_kernel<<<(BATCH * SEQ * DIM / 4) / 256, 256>>>(out);
}

// round 13
// speedup vs baseline: 1.6347x; 1.0785x over previous
#include <cuda_runtime.h>
#include <cuda_bf16.h>
#include <cuda_fp16.h>
#include <math.h>
#include <stdint.h>

#define BATCH 8
#define SEQ   2048
#define DIM   512
#define ITERS 12
#define KSPLIT 2

typedef __nv_bfloat16 bf16;

// ---------------- scratch (static device memory; no allocations) --------------
__device__ __half g_qhi[(size_t)BATCH * SEQ * DIM];   // Q fp16 hi
__device__ __half g_qlo[(size_t)BATCH * SEQ * DIM];   // Q fp16 lo
__device__ __half g_k16[(size_t)BATCH * SEQ * DIM];   // K fp16 single
__device__ __half g_vt16[(size_t)BATCH * DIM * SEQ];  // V^T fp16 single
__device__ __half g_sp16[(size_t)BATCH * SEQ * SEQ];  // scores -> probs (fp16, in place)
__device__ float g_part[KSPLIT][(size_t)BATCH * SEQ * DIM];  // pv partials
__device__ float g_w[SEQ];
__device__ float g_blend;
__device__ float g_meanV[BATCH * DIM];
__device__ float g_pa[4096];
__device__ float g_pb[4096];

// ---------------- helpers ----------------------------------------------------
__device__ __forceinline__ uint32_t smem_u32(const void* p) {
    uint32_t a;
    asm("{ .reg .u64 t; cvta.to.shared.u64 t, %1; cvt.u32.u64 %0, t; }" : "=r"(a) : "l"(p));
    return a;
}
__device__ __forceinline__ void hmma16816f(float c[4], const uint32_t a[4], const uint32_t b[2]) {
    asm volatile(
        "mma.sync.aligned.m16n8k16.row.col.f32.f16.f16.f32 "
        "{%0,%1,%2,%3}, {%4,%5,%6,%7}, {%8,%9}, {%0,%1,%2,%3};"
        : "+f"(c[0]), "+f"(c[1]), "+f"(c[2]), "+f"(c[3])
        : "r"(a[0]), "r"(a[1]), "r"(a[2]), "r"(a[3]), "r"(b[0]), "r"(b[1]));
}
__device__ __forceinline__ void ldsm_x4(uint32_t r[4], uint32_t addr) {
    asm volatile("ldmatrix.sync.aligned.m8n8.x4.shared.b16 {%0,%1,%2,%3}, [%4];"
                 : "=r"(r[0]), "=r"(r[1]), "=r"(r[2]), "=r"(r[3]) : "r"(addr));
}
#define CP_ASYNC16(saddr, gptr) \
    asm volatile("cp.async.cg.shared.global [%0], [%1], 16;" :: "r"(saddr), "l"(gptr))
#define CP_COMMIT() asm volatile("cp.async.commit_group;" ::: "memory")
#define CP_WAIT(n)  asm volatile("cp.async.wait_group %0;" :: "n"(n) : "memory")

__device__ __forceinline__ float wredmax(float v) {
    #pragma unroll
    for (int o = 16; o > 0; o >>= 1) v = fmaxf(v, __shfl_xor_sync(0xffffffffu, v, o));
    return v;
}
__device__ __forceinline__ float wredmin(float v) {
    #pragma unroll
    for (int o = 16; o > 0; o >>= 1) v = fminf(v, __shfl_xor_sync(0xffffffffu, v, o));
    return v;
}
__device__ __forceinline__ float wredsum(float v) {
    #pragma unroll
    for (int o = 16; o > 0; o >>= 1) v += __shfl_xor_sync(0xffffffffu, v, o);
    return v;
}

// ---------------- prep: dragon pattern + softplus weights + blend scalar ------
__global__ void prep_kernel(const float* __restrict__ ps, const float* __restrict__ pb,
                            const float* __restrict__ w1, const float* __restrict__ b1,
                            const float* __restrict__ w2, const float* __restrict__ b2) {
    const int tid = threadIdx.x, nt = blockDim.x;
    const int lane = tid & 31, wid = tid >> 5;
    __shared__ float redmn[32], redmx[32];
    __shared__ float s_mn, s_mx;
    const int it = 11;

    float* cur = g_pa;
    float* tmp = g_pb;
    if (tid == 0) cur[0] = 0.5f;
    __syncthreads();

    int len = 1;
    const float k3 = 1.0f / 3.0f;
    for (int iter = 1; iter < ITERS; ++iter) {
        const int nl = 2 * len + 1;
        for (int j = tid; j < nl; j += nt) {
            float val;
            if (j < len)       val = cur[j];
            else if (j == len) val = 0.5f;
            else               val = 1.0f - cur[nl - 1 - j];
            tmp[j] = val;
        }
        __syncthreads();
        float lmn = 3.4e38f, lmx = -3.4e38f;
        for (int j = tid; j < nl; j += nt) {
            float l = (j > 0)      ? tmp[j - 1] : 0.0f;
            float c = tmp[j];
            float r = (j + 1 < nl) ? tmp[j + 1] : 0.0f;
            float val = l * k3 + c * k3 + r * k3;
            cur[j] = val;
            lmn = fminf(lmn, val);
            lmx = fmaxf(lmx, val);
        }
        lmn = wredmin(lmn);
        lmx = wredmax(lmx);
        if (lane == 0) { redmn[wid] = lmn; redmx[wid] = lmx; }
        __syncthreads();
        if (wid == 0) {
            float a = (lane < nt / 32) ? redmn[lane] : 3.4e38f;
            float c = (lane < nt / 32) ? redmx[lane] : -3.4e38f;
            a = wredmin(a);
            c = wredmax(c);
            if (lane == 0) { s_mn = a; s_mx = c; }
        }
        __syncthreads();
        const float mn = s_mn, mx = s_mx;
        for (int j = tid; j < nl; j += nt)
            cur[j] = (cur[j] - mn) / (mx - mn + 1e-8f);
        __syncthreads();
        len = nl;
    }

    const float sc = ps[it], bi = pb[it];
    for (int s = tid; s < SEQ; s += nt) {
        double x = (double)s / (double)(SEQ - 1);
        double t = x * (double)(len - 1);
        int i0 = (int)t;
        if (i0 > len - 2) i0 = len - 2;
        double fr = t - (double)i0;
        float w = (float)((1.0 - fr) * (double)cur[i0] + fr * (double)cur[i0 + 1]);
        float z = fmaf(w, sc, bi);
        g_w[s] = fmaxf(z, 0.0f) + log1pf(expf(-fabsf(z)));
    }

    if (tid == 0) {
        float acc = b2[0];
        for (int j = 0; j < 64; ++j) {
            float h = w1[it * 64 + j] + b1[j];
            if (h > 0.0f) acc = fmaf(h, w2[j], acc);
        }
        g_blend = 1.0f / (1.0f + expf(-acc));
    }
}

// ---------------- column mean of V per batch -----------------------------------
__global__ void meanv_kernel(const float* __restrict__ V) {
    const int b = blockIdx.y;
    const int d = (blockIdx.x << 7) + threadIdx.x;
    const float* p = V + (size_t)b * SEQ * DIM + d;
    float a0 = 0.f, a1 = 0.f, a2 = 0.f, a3 = 0.f;
    #pragma unroll 4
    for (int k = 0; k < SEQ; k += 4) {
        a0 += p[(size_t)(k + 0) * DIM];
        a1 += p[(size_t)(k + 1) * DIM];
        a2 += p[(size_t)(k + 2) * DIM];
        a3 += p[(size_t)(k + 3) * DIM];
    }
    g_meanV[b * DIM + d] = (a0 + a1 + a2 + a3) * (1.0f / SEQ);
}

// ---------------- split Q (fp16 hi/lo) and K (fp16 single) -----------------------
__global__ __launch_bounds__(256) void splitqk_kernel(const float* __restrict__ Q,
                                                      const float* __restrict__ K) {
    const size_t i = (size_t)blockIdx.x * 256 + threadIdx.x;
    if (blockIdx.y == 0) {
        float4 v = ((const float4*)Q)[i];
        __half h0 = __float2half_rn(v.x), h1 = __float2half_rn(v.y);
        __half h2 = __float2half_rn(v.z), h3 = __float2half_rn(v.w);
        __half2 hh[2] = {__halves2half2(h0, h1), __halves2half2(h2, h3)};
        __half2 ll[2] = {
            __floats2half2_rn(v.x - __half2float(h0), v.y - __half2float(h1)),
            __floats2half2_rn(v.z - __half2float(h2), v.w - __half2float(h3))};
        ((uint2*)g_qhi)[i] = *(uint2*)hh;
        ((uint2*)g_qlo)[i] = *(uint2*)ll;
    } else {
        float4 v = ((const float4*)K)[i];
        __half2 kk[2] = {__floats2half2_rn(v.x, v.y), __floats2half2_rn(v.z, v.w)};
        ((uint2*)g_k16)[i] = *(uint2*)kk;
    }
}

// ---------------- transpose V: Vt[b][d][s] fp16 single ---------------------------
__global__ void splitv_kernel(const float* __restrict__ V) {
    __shared__ float t[32][33];
    const int b = blockIdx.z;
    const int s0 = blockIdx.x << 5, d0 = blockIdx.y << 5;
    const int tx = threadIdx.x, ty = threadIdx.y;
    const float* src = V + ((size_t)b * SEQ + s0) * DIM + d0 + tx;
    #pragma unroll
    for (int i = 0; i < 32; i += 8) t[ty + i][tx] = src[(size_t)(ty + i) * DIM];
    __syncthreads();
    #pragma unroll
    for (int i = 0; i < 32; i += 8) {
        float x = t[tx][ty + i];
        size_t o = ((size_t)b * DIM + d0 + ty + i) * SEQ + s0 + tx;
        g_vt16[o] = __float2half_rn(x);
    }
}

#define TILE_B 8192u                 // bytes per 128x32 16-bit tile

// =================================================================================
// Scores GEMM core: 2-term fp16. C[128x128] = Qhi*K + Qlo*K.
// 256 threads, 2x4 warp grid, warp tile 64x32. XOR-swizzled 64B rows.
// Stage = [Ahi, Alo, B] = 24 KB; 3 stages; one barrier per 32-K chunk.
// =================================================================================
#define SC_STAGE_B (3u * TILE_B)        // 24576
#define SC_DSMEM   (3u * SC_STAGE_B)    // 73728

#define SC_ISSUE_CHUNK(bufbase, kb) do { \
    CP_ASYNC16((bufbase) + 0u * TILE_B + st0, aHi + g0a + (kb)); \
    CP_ASYNC16((bufbase) + 0u * TILE_B + st1, aHi + g1a + (kb)); \
    CP_ASYNC16((bufbase) + 1u * TILE_B + st0, aLo + g0a + (kb)); \
    CP_ASYNC16((bufbase) + 1u * TILE_B + st1, aLo + g1a + (kb)); \
    CP_ASYNC16((bufbase) + 2u * TILE_B + st0, bK + g0b + (kb)); \
    CP_ASYNC16((bufbase) + 2u * TILE_B + st1, bK + g1b + (kb)); \
    CP_COMMIT(); \
} while (0)

template <int LDA, int LDB, int CPS>
__device__ __forceinline__ void scores_mainloop(
    const __half* aHi, const __half* aLo, const __half* bK,
    __half* smem, float c[4][4][4])
{
    const int tid = threadIdx.x;
    const int wid = tid >> 5, lane = tid & 31;
    const int wm = wid & 1, wn = wid >> 1;

    const uint32_t smem_base = smem_u32(smem);

    const int r0 = tid >> 2,         c0 = tid & 3;
    const int r1 = (256 + tid) >> 2, c1 = tid & 3;
    const uint32_t st0 = (uint32_t)(r0 * 64 + ((c0 ^ ((r0 >> 1) & 3)) << 4));
    const uint32_t st1 = (uint32_t)(r1 * 64 + ((c1 ^ ((r1 >> 1) & 3)) << 4));
    const size_t g0a = (size_t)r0 * LDA + c0 * 8, g1a = (size_t)r1 * LDA + c1 * 8;
    const size_t g0b = (size_t)r0 * LDB + c0 * 8, g1b = (size_t)r1 * LDB + c1 * 8;

    const int a_row = wm * 64 + (lane & 15);
    const int a_hi  = (lane >> 4) & 1;
    const int xa    = (a_row >> 1) & 3;
    const uint32_t a_base = (uint32_t)(a_row * 64);
    const int b_row = wn * 32 + (lane & 7) + ((lane & 16) ? 8 : 0);
    const int b_hi  = (lane >> 3) & 1;
    const int xb    = (b_row >> 1) & 3;
    const uint32_t b_base = (uint32_t)(b_row * 64);

    SC_ISSUE_CHUNK(smem_base, 0);
    SC_ISSUE_CHUNK(smem_base + SC_STAGE_B, 32);

    #pragma unroll 1
    for (int ch = 0; ch < CPS; ++ch) {
        if (ch + 1 < CPS) { CP_WAIT(1); } else { CP_WAIT(0); }
        __syncthreads();
        if (ch + 2 < CPS) {
            const uint32_t nb = smem_base + (uint32_t)((ch + 2) % 3) * SC_STAGE_B;
            const int kb = (ch + 2) * 32;
            SC_ISSUE_CHUNK(nb, kb);
        }

        const uint32_t bb = smem_base + (uint32_t)(ch % 3) * SC_STAGE_B;
        #pragma unroll
        for (int ks = 0; ks < 2; ++ks) {
            const uint32_t ka  = (uint32_t)(((ks * 2 + a_hi) ^ xa) << 4);
            const uint32_t kb2 = (uint32_t)(((ks * 2 + b_hi) ^ xb) << 4);
            uint32_t ah[4][4], bh[2][4];
            #pragma unroll
            for (int mt = 0; mt < 4; ++mt)
                ldsm_x4(ah[mt], bb + 0u * TILE_B + a_base + mt * 1024u + ka);
            #pragma unroll
            for (int ntp = 0; ntp < 2; ++ntp)
                ldsm_x4(bh[ntp], bb + 2u * TILE_B + b_base + ntp * 1024u + kb2);
            #pragma unroll
            for (int mt = 0; mt < 4; ++mt)
                #pragma unroll
                for (int nt = 0; nt < 4; ++nt)
                    hmma16816f(c[mt][nt], ah[mt], &bh[nt >> 1][(nt & 1) * 2]);
            {
                uint32_t al[4][4];
                #pragma unroll
                for (int mt = 0; mt < 4; ++mt)
                    ldsm_x4(al[mt], bb + 1u * TILE_B + a_base + mt * 1024u + ka);
                #pragma unroll
                for (int mt = 0; mt < 4; ++mt)
                    #pragma unroll
                    for (int nt = 0; nt < 4; ++nt)
                        hmma16816f(c[mt][nt], al[mt], &bh[nt >> 1][(nt & 1) * 2]);
            }
        }
    }
}

// ---------------- GEMM1: S = (Q.K^T) * w[n]/sqrt(D) -> fp16 ----------------------
__global__ __launch_bounds__(256, 2) void scores_mma_kernel() {
    extern __shared__ __half dynsmem_h[];
    __shared__ float s_ws[128];

    const int tid = threadIdx.x, wid = tid >> 5, lane = tid & 31;
    const int grp = lane >> 2, t4 = lane & 3;
    const int wm = wid & 1, wn = wid >> 1;
    const int b = blockIdx.z, m0 = blockIdx.y << 7, n0 = blockIdx.x << 7;

    if (tid < 128) s_ws[tid] = g_w[n0 + tid] * 0.04419417382415922f;

    const size_t boff = (size_t)b * SEQ * DIM;
    const __half* A0 = g_qhi + boff + (size_t)m0 * DIM;
    const __half* A1 = g_qlo + boff + (size_t)m0 * DIM;
    const __half* B0 = g_k16 + boff + (size_t)n0 * DIM;

    float c[4][4][4];
    #pragma unroll
    for (int i = 0; i < 4; ++i)
        #pragma unroll
        for (int j = 0; j < 4; ++j)
            #pragma unroll
            for (int q = 0; q < 4; ++q) c[i][j][q] = 0.f;

    scores_mainloop<DIM, DIM, DIM / 32>(A0, A1, B0, dynsmem_h, c);

    __half* sb = g_sp16 + (size_t)b * SEQ * SEQ;
    #pragma unroll
    for (int mt = 0; mt < 4; ++mt) {
        #pragma unroll
        for (int nt = 0; nt < 4; ++nt) {
            const int col_l = wn * 32 + nt * 8 + t4 * 2;
            const int col = n0 + col_l;
            const float w0 = s_ws[col_l], w1v = s_ws[col_l + 1];
            #pragma unroll
            for (int rr = 0; rr < 2; ++rr) {
                const int row = m0 + wm * 64 + mt * 16 + grp + rr * 8;
                __half2 o = __floats2half2_rn(c[mt][nt][2 * rr] * w0,
                                              c[mt][nt][2 * rr + 1] * w1v);
                *(__half2*)(sb + (size_t)row * SEQ + col) = o;
            }
        }
    }
}

// ---------------- softmax over fp16 scores -> fp16 probs (in place) ---------------
__global__ __launch_bounds__(256) void softmax_kernel2() {
    const size_t row = blockIdx.x;
    __half* p = g_sp16 + row * SEQ;
    const int tid = threadIdx.x, lane = tid & 31, wid = tid >> 5;
    __shared__ float red[8];

    uint4 u = ((const uint4*)p)[tid];
    float x[8];
    const __half2* h2 = (const __half2*)&u;
    #pragma unroll
    for (int q = 0; q < 4; ++q) {
        float2 a = __half22float2(h2[q]);
        x[2 * q]     = a.x;
        x[2 * q + 1] = a.y;
    }

    float m = x[0];
    #pragma unroll
    for (int i = 1; i < 8; ++i) m = fmaxf(m, x[i]);
    m = wredmax(m);
    if (lane == 0) red[wid] = m;
    __syncthreads();
    m = red[0];
    #pragma unroll
    for (int i = 1; i < 8; ++i) m = fmaxf(m, red[i]);
    __syncthreads();

    float e[8], s = 0.f;
    #pragma unroll
    for (int i = 0; i < 8; ++i) { e[i] = __expf(x[i] - m); s += e[i]; }
    s = wredsum(s);
    if (lane == 0) red[wid] = s;
    __syncthreads();
    float tot = 0.f;
    #pragma unroll
    for (int i = 0; i < 8; ++i) tot += red[i];
    const float inv = 1.0f / tot;

    __half2 hh[4];
    #pragma unroll
    for (int q = 0; q < 4; ++q)
        hh[q] = __floats2half2_rn(e[2 * q] * inv, e[2 * q + 1] * inv);
    ((uint4*)p)[tid] = *(uint4*)hh;
}

// =================================================================================
// PV GEMM core: 1-term fp16, K-chunk 64 (two 32-sub-tiles per stage).
// Stage = [A_k0, A_k1, B_k0, B_k1] = 32 KB; 3 stages.
// =================================================================================
#define PV_STAGE_B (4u * TILE_B)        // 32768
#define PV_DSMEM   (3u * PV_STAGE_B)    // 98304

#define PV_ISSUE_CHUNK(bufbase, kb) do { \
    CP_ASYNC16((bufbase) + 0u * TILE_B + st0, aP + g0a + (kb)); \
    CP_ASYNC16((bufbase) + 0u * TILE_B + st1, aP + g1a + (kb)); \
    CP_ASYNC16((bufbase) + 1u * TILE_B + st0, aP + g0a + (kb) + 32); \
    CP_ASYNC16((bufbase) + 1u * TILE_B + st1, aP + g1a + (kb) + 32); \
    CP_ASYNC16((bufbase) + 2u * TILE_B + st0, bV + g0b + (kb)); \
    CP_ASYNC16((bufbase) + 2u * TILE_B + st1, bV + g1b + (kb)); \
    CP_ASYNC16((bufbase) + 3u * TILE_B + st0, bV + g0b + (kb) + 32); \
    CP_ASYNC16((bufbase) + 3u * TILE_B + st1, bV + g1b + (kb) + 32); \
    CP_COMMIT(); \
} while (0)

template <int LDA, int LDB, int CPS>   // CPS = number of 64-K chunks
__device__ __forceinline__ void pv_mainloop(
    const __half* aP, const __half* bV,
    __half* smem, float c[4][4][4])
{
    const int tid = threadIdx.x;
    const int wid = tid >> 5, lane = tid & 31;
    const int wm = wid & 1, wn = wid >> 1;

    const uint32_t smem_base = smem_u32(smem);

    const int r0 = tid >> 2,         c0 = tid & 3;
    const int r1 = (256 + tid) >> 2, c1 = tid & 3;
    const uint32_t st0 = (uint32_t)(r0 * 64 + ((c0 ^ ((r0 >> 1) & 3)) << 4));
    const uint32_t st1 = (uint32_t)(r1 * 64 + ((c1 ^ ((r1 >> 1) & 3)) << 4));
    const size_t g0a = (size_t)r0 * LDA + c0 * 8, g1a = (size_t)r1 * LDA + c1 * 8;
    const size_t g0b = (size_t)r0 * LDB + c0 * 8, g1b = (size_t)r1 * LDB + c1 * 8;

    const int a_row = wm * 64 + (lane & 15);
    const int a_hi  = (lane >> 4) & 1;
    const int xa    = (a_row >> 1) & 3;
    const uint32_t a_base = (uint32_t)(a_row * 64);
    const int b_row = wn * 32 + (lane & 7) + ((lane & 16) ? 8 : 0);
    const int b_hi  = (lane >> 3) & 1;
    const int xb    = (b_row >> 1) & 3;
    const uint32_t b_base = (uint32_t)(b_row * 64);

    PV_ISSUE_CHUNK(smem_base, 0);
    PV_ISSUE_CHUNK(smem_base + PV_STAGE_B, 64);

    #pragma unroll 1
    for (int ch = 0; ch < CPS; ++ch) {
        if (ch + 1 < CPS) { CP_WAIT(1); } else { CP_WAIT(0); }
        __syncthreads();
        if (ch + 2 < CPS) {
            const uint32_t nb = smem_base + (uint32_t)((ch + 2) % 3) * PV_STAGE_B;
            const int kb = (ch + 2) * 64;
            PV_ISSUE_CHUNK(nb, kb);
        }

        const uint32_t bb = smem_base + (uint32_t)(ch % 3) * PV_STAGE_B;
        #pragma unroll
        for (int sub = 0; sub < 2; ++sub) {
            #pragma unroll
            for (int ks = 0; ks < 2; ++ks) {
                const uint32_t ka  = (uint32_t)(((ks * 2 + a_hi) ^ xa) << 4);
                const uint32_t kb2 = (uint32_t)(((ks * 2 + b_hi) ^ xb) << 4);
                uint32_t ah[4][4], bh[2][4];
                #pragma unroll
                for (int mt = 0; mt < 4; ++mt)
                    ldsm_x4(ah[mt], bb + (uint32_t)sub * TILE_B + a_base + mt * 1024u + ka);
                #pragma unroll
                for (int ntp = 0; ntp < 2; ++ntp)
                    ldsm_x4(bh[ntp], bb + (2u + sub) * TILE_B + b_base + ntp * 1024u + kb2);
                #pragma unroll
                for (int mt = 0; mt < 4; ++mt)
                    #pragma unroll
                    for (int nt = 0; nt < 4; ++nt)
                        hmma16816f(c[mt][nt], ah[mt], &bh[nt >> 1][(nt & 1) * 2]);
            }
        }
    }
}

// ---------------- GEMM2 (K-split): part[s] = P[:, ks] . V[ks, :] ------------------
__global__ __launch_bounds__(256, 2) void pv_mma_kernel() {
    extern __shared__ __half dynsmem_h[];

    const int tid = threadIdx.x, wid = tid >> 5, lane = tid & 31;
    const int grp = lane >> 2, t4 = lane & 3;
    const int wm = wid & 1, wn = wid >> 1;
    const int b = blockIdx.z >> 1, s = blockIdx.z & 1;
    const int m0 = blockIdx.y << 7, n0 = blockIdx.x << 7;
    const int k0 = s * (SEQ / KSPLIT);

    const __half* A0 = g_sp16 + (size_t)b * SEQ * SEQ + (size_t)m0 * SEQ + k0;
    const __half* B0 = g_vt16 + (size_t)b * DIM * SEQ + (size_t)n0 * SEQ + k0;

    float c[4][4][4];
    #pragma unroll
    for (int i = 0; i < 4; ++i)
        #pragma unroll
        for (int j = 0; j < 4; ++j)
            #pragma unroll
            for (int q = 0; q < 4; ++q) c[i][j][q] = 0.f;

    pv_mainloop<SEQ, SEQ, (SEQ / KSPLIT) / 64>(A0, B0, dynsmem_h, c);

    float* pout = g_part[s] + (size_t)b * SEQ * DIM;
    #pragma unroll
    for (int mt = 0; mt < 4; ++mt) {
        #pragma unroll
        for (int nt = 0; nt < 4; ++nt) {
            const int col = n0 + wn * 32 + nt * 8 + t4 * 2;
            #pragma unroll
            for (int rr = 0; rr < 2; ++rr) {
                const int row = m0 + wm * 64 + mt * 16 + grp + rr * 8;
                float2 o = make_float2(c[mt][nt][2 * rr], c[mt][nt][2 * rr + 1]);
                *(float2*)(pout + (size_t)row * DIM + col) = o;
            }
        }
    }
}

// ---------------- reduce: out = blend * sum(parts) + (1-blend) * meanV -----------
__global__ __launch_bounds__(256) void reduce_kernel(float* __restrict__ out) {
    const size_t i4 = (size_t)blockIdx.x * 256 + threadIdx.x;   // float4 index
    const float blend = g_blend;
    const float ob = 1.0f - blend;
    const size_t ei = i4 * 4;
    const int b = (int)(ei / ((size_t)SEQ * DIM));
    const int d = (int)(ei % DIM);

    float4 p0 = ((const float4*)g_part[0])[i4];
    float4 p1 = ((const float4*)g_part[1])[i4];
    const float* mv = g_meanV + b * DIM + d;

    float4 o;
    o.x = fmaf(blend, p0.x + p1.x, ob * mv[0]);
    o.y = fmaf(blend, p0.y + p1.y, ob * mv[1]);
    o.z = fmaf(blend, p0.z + p1.z, ob * mv[2]);
    o.w = fmaf(blend, p0.w + p1.w, ob * mv[3]);
    ((float4*)out)[i4] = o;
}

// ---------------- launch -----------------------------------------------------------
extern "C" void kernel_launch(void* const* d_in, const int* in_sizes, int n_in,
                              void* d_out, int out_size) {
    const float* q  = (const float*)d_in[0];
    const float* k  = (const float*)d_in[1];
    const float* v  = (const float*)d_in[2];
    const float* ps = (const float*)d_in[3];
    const float* pb = (const float*)d_in[4];
    const float* w1 = (const float*)d_in[5];
    const float* b1 = (const float*)d_in[6];
    const float* w2 = (const float*)d_in[7];
    const float* b2 = (const float*)d_in[8];
    float* out = (float*)d_out;

    static bool attr_set = false;
    if (!attr_set) {
        cudaFuncSetAttribute(scores_mma_kernel,
                             cudaFuncAttributeMaxDynamicSharedMemorySize, SC_DSMEM);
        cudaFuncSetAttribute(pv_mma_kernel,
                             cudaFuncAttributeMaxDynamicSharedMemorySize, PV_DSMEM);
        attr_set = true;
    }

    prep_kernel<<<1, 1024>>>(ps, pb, w1, b1, w2, b2);
    splitqk_kernel<<<dim3((BATCH * SEQ * DIM / 4) / 256, 2), 256>>>(q, k);
    splitv_kernel<<<dim3(SEQ / 32, DIM / 32, BATCH), dim3(32, 8)>>>(v);
    scores_mma_kernel<<<dim3(SEQ / 128, SEQ / 128, BATCH), 256, SC_DSMEM>>>();
    meanv_kernel<<<dim3(DIM / 128, BATCH), 128>>>(v);
    softmax_kernel2<<<BATCH * SEQ, 256>>>();
    pv_mma_kernel<<<dim3(DIM / 128, SEQ / 128, BATCH * KSPLIT), 256, PV_DSMEM>>>();
    reduce_kernel<<<(BATCH * SEQ * DIM / 4) / 256, 256>>>(out);
}

// round 14
// speedup vs baseline: 1.6877x; 1.0324x over previous
#include <cuda_runtime.h>
#include <cuda_bf16.h>
#include <cuda_fp16.h>
#include <math.h>
#include <stdint.h>

#define BATCH 8
#define SEQ   2048
#define DIM   512
#define ITERS 12
#define KSPLIT 2

typedef __nv_bfloat16 bf16;

// ---------------- scratch (static device memory; no allocations) --------------
__device__ __half g_qhi[(size_t)BATCH * SEQ * DIM];   // Q fp16 hi
__device__ __half g_qlo[(size_t)BATCH * SEQ * DIM];   // Q fp16 lo
__device__ __half g_k16[(size_t)BATCH * SEQ * DIM];   // K fp16 single
__device__ __half g_vt16[(size_t)BATCH * DIM * SEQ];  // V^T fp16 single
__device__ __half g_sp16[(size_t)BATCH * SEQ * SEQ];  // scores -> probs (fp16, in place)
__device__ float g_part[KSPLIT][(size_t)BATCH * SEQ * DIM];  // pv partials
__device__ float g_w[SEQ];
__device__ float g_blend;
__device__ float g_meanV[BATCH * DIM];
__device__ float g_pa[4096];
__device__ float g_pb[4096];

// ---------------- helpers ----------------------------------------------------
__device__ __forceinline__ uint32_t smem_u32(const void* p) {
    uint32_t a;
    asm("{ .reg .u64 t; cvta.to.shared.u64 t, %1; cvt.u32.u64 %0, t; }" : "=r"(a) : "l"(p));
    return a;
}
__device__ __forceinline__ void hmma16816f(float c[4], const uint32_t a[4], const uint32_t b[2]) {
    asm volatile(
        "mma.sync.aligned.m16n8k16.row.col.f32.f16.f16.f32 "
        "{%0,%1,%2,%3}, {%4,%5,%6,%7}, {%8,%9}, {%0,%1,%2,%3};"
        : "+f"(c[0]), "+f"(c[1]), "+f"(c[2]), "+f"(c[3])
        : "r"(a[0]), "r"(a[1]), "r"(a[2]), "r"(a[3]), "r"(b[0]), "r"(b[1]));
}
__device__ __forceinline__ void ldsm_x4(uint32_t r[4], uint32_t addr) {
    asm volatile("ldmatrix.sync.aligned.m8n8.x4.shared.b16 {%0,%1,%2,%3}, [%4];"
                 : "=r"(r[0]), "=r"(r[1]), "=r"(r[2]), "=r"(r[3]) : "r"(addr));
}
#define CP_ASYNC16(saddr, gptr) \
    asm volatile("cp.async.cg.shared.global [%0], [%1], 16;" :: "r"(saddr), "l"(gptr))
#define CP_COMMIT() asm volatile("cp.async.commit_group;" ::: "memory")
#define CP_WAIT(n)  asm volatile("cp.async.wait_group %0;" :: "n"(n) : "memory")

__device__ __forceinline__ float wredmax(float v) {
    #pragma unroll
    for (int o = 16; o > 0; o >>= 1) v = fmaxf(v, __shfl_xor_sync(0xffffffffu, v, o));
    return v;
}
__device__ __forceinline__ float wredmin(float v) {
    #pragma unroll
    for (int o = 16; o > 0; o >>= 1) v = fminf(v, __shfl_xor_sync(0xffffffffu, v, o));
    return v;
}
__device__ __forceinline__ float wredsum(float v) {
    #pragma unroll
    for (int o = 16; o > 0; o >>= 1) v += __shfl_xor_sync(0xffffffffu, v, o);
    return v;
}

// ---------------- prep: dragon pattern + softplus weights + blend scalar ------
__global__ void prep_kernel(const float* __restrict__ ps, const float* __restrict__ pb,
                            const float* __restrict__ w1, const float* __restrict__ b1,
                            const float* __restrict__ w2, const float* __restrict__ b2) {
    const int tid = threadIdx.x, nt = blockDim.x;
    const int lane = tid & 31, wid = tid >> 5;
    __shared__ float redmn[32], redmx[32];
    __shared__ float s_mn, s_mx;
    const int it = 11;

    float* cur = g_pa;
    float* tmp = g_pb;
    if (tid == 0) cur[0] = 0.5f;
    __syncthreads();

    int len = 1;
    const float k3 = 1.0f / 3.0f;
    for (int iter = 1; iter < ITERS; ++iter) {
        const int nl = 2 * len + 1;
        for (int j = tid; j < nl; j += nt) {
            float val;
            if (j < len)       val = cur[j];
            else if (j == len) val = 0.5f;
            else               val = 1.0f - cur[nl - 1 - j];
            tmp[j] = val;
        }
        __syncthreads();
        float lmn = 3.4e38f, lmx = -3.4e38f;
        for (int j = tid; j < nl; j += nt) {
            float l = (j > 0)      ? tmp[j - 1] : 0.0f;
            float c = tmp[j];
            float r = (j + 1 < nl) ? tmp[j + 1] : 0.0f;
            float val = l * k3 + c * k3 + r * k3;
            cur[j] = val;
            lmn = fminf(lmn, val);
            lmx = fmaxf(lmx, val);
        }
        lmn = wredmin(lmn);
        lmx = wredmax(lmx);
        if (lane == 0) { redmn[wid] = lmn; redmx[wid] = lmx; }
        __syncthreads();
        if (wid == 0) {
            float a = (lane < nt / 32) ? redmn[lane] : 3.4e38f;
            float c = (lane < nt / 32) ? redmx[lane] : -3.4e38f;
            a = wredmin(a);
            c = wredmax(c);
            if (lane == 0) { s_mn = a; s_mx = c; }
        }
        __syncthreads();
        const float mn = s_mn, mx = s_mx;
        for (int j = tid; j < nl; j += nt)
            cur[j] = (cur[j] - mn) / (mx - mn + 1e-8f);
        __syncthreads();
        len = nl;
    }

    const float sc = ps[it], bi = pb[it];
    for (int s = tid; s < SEQ; s += nt) {
        double x = (double)s / (double)(SEQ - 1);
        double t = x * (double)(len - 1);
        int i0 = (int)t;
        if (i0 > len - 2) i0 = len - 2;
        double fr = t - (double)i0;
        float w = (float)((1.0 - fr) * (double)cur[i0] + fr * (double)cur[i0 + 1]);
        float z = fmaf(w, sc, bi);
        g_w[s] = fmaxf(z, 0.0f) + log1pf(expf(-fabsf(z)));
    }

    if (tid == 0) {
        float acc = b2[0];
        for (int j = 0; j < 64; ++j) {
            float h = w1[it * 64 + j] + b1[j];
            if (h > 0.0f) acc = fmaf(h, w2[j], acc);
        }
        g_blend = 1.0f / (1.0f + expf(-acc));
    }
}

// ---------------- column mean of V per batch -----------------------------------
__global__ void meanv_kernel(const float* __restrict__ V) {
    const int b = blockIdx.y;
    const int d = (blockIdx.x << 7) + threadIdx.x;
    const float* p = V + (size_t)b * SEQ * DIM + d;
    float a0 = 0.f, a1 = 0.f, a2 = 0.f, a3 = 0.f;
    #pragma unroll 4
    for (int k = 0; k < SEQ; k += 4) {
        a0 += p[(size_t)(k + 0) * DIM];
        a1 += p[(size_t)(k + 1) * DIM];
        a2 += p[(size_t)(k + 2) * DIM];
        a3 += p[(size_t)(k + 3) * DIM];
    }
    g_meanV[b * DIM + d] = (a0 + a1 + a2 + a3) * (1.0f / SEQ);
}

// ---------------- split Q (fp16 hi/lo) and K (fp16 single) -----------------------
__global__ __launch_bounds__(256) void splitqk_kernel(const float* __restrict__ Q,
                                                      const float* __restrict__ K) {
    const size_t i = (size_t)blockIdx.x * 256 + threadIdx.x;
    if (blockIdx.y == 0) {
        float4 v = ((const float4*)Q)[i];
        __half h0 = __float2half_rn(v.x), h1 = __float2half_rn(v.y);
        __half h2 = __float2half_rn(v.z), h3 = __float2half_rn(v.w);
        __half2 hh[2] = {__halves2half2(h0, h1), __halves2half2(h2, h3)};
        __half2 ll[2] = {
            __floats2half2_rn(v.x - __half2float(h0), v.y - __half2float(h1)),
            __floats2half2_rn(v.z - __half2float(h2), v.w - __half2float(h3))};
        ((uint2*)g_qhi)[i] = *(uint2*)hh;
        ((uint2*)g_qlo)[i] = *(uint2*)ll;
    } else {
        float4 v = ((const float4*)K)[i];
        __half2 kk[2] = {__floats2half2_rn(v.x, v.y), __floats2half2_rn(v.z, v.w)};
        ((uint2*)g_k16)[i] = *(uint2*)kk;
    }
}

// ---------------- transpose V: Vt[b][d][s] fp16 single ---------------------------
__global__ void splitv_kernel(const float* __restrict__ V) {
    __shared__ float t[32][33];
    const int b = blockIdx.z;
    const int s0 = blockIdx.x << 5, d0 = blockIdx.y << 5;
    const int tx = threadIdx.x, ty = threadIdx.y;
    const float* src = V + ((size_t)b * SEQ + s0) * DIM + d0 + tx;
    #pragma unroll
    for (int i = 0; i < 32; i += 8) t[ty + i][tx] = src[(size_t)(ty + i) * DIM];
    __syncthreads();
    #pragma unroll
    for (int i = 0; i < 32; i += 8) {
        float x = t[tx][ty + i];
        size_t o = ((size_t)b * DIM + d0 + ty + i) * SEQ + s0 + tx;
        g_vt16[o] = __float2half_rn(x);
    }
}

#define TILE_B   8192u               // bytes per 128x32 16-bit tile
#define TILE64_B 16384u              // bytes per 128x64 16-bit tile

// =================================================================================
// Scores GEMM core: 2-term fp16, K-chunk 64, 128B swizzled rows (c ^= row&7).
// 256 threads, 2x4 warp grid, warp tile 64x32.
// Stage = [Ahi, Alo, K] = 48 KB; 2 stages (96 KB); one barrier per 64-K chunk.
// =================================================================================
#define SC_STAGE_B (3u * TILE64_B)      // 49152
#define SC_DSMEM   (2u * SC_STAGE_B)    // 98304

#define SC_ISSUE_CHUNK(bufbase, kb) do { \
    _Pragma("unroll") \
    for (int i = 0; i < 4; ++i) { \
        CP_ASYNC16((bufbase) + 0u * TILE64_B + st[i], aHi + ga[i] + (kb)); \
        CP_ASYNC16((bufbase) + 1u * TILE64_B + st[i], aLo + ga[i] + (kb)); \
        CP_ASYNC16((bufbase) + 2u * TILE64_B + st[i], bK + gb[i] + (kb)); \
    } \
    CP_COMMIT(); \
} while (0)

template <int LDA, int LDB, int CPS>   // CPS = number of 64-K chunks
__device__ __forceinline__ void scores_mainloop(
    const __half* aHi, const __half* aLo, const __half* bK,
    __half* smem, float c[4][4][4])
{
    const int tid = threadIdx.x;
    const int wid = tid >> 5, lane = tid & 31;
    const int wm = wid & 1, wn = wid >> 1;

    const uint32_t smem_base = smem_u32(smem);

    // cp.async store offsets: 1024 16B-chunks per tile; row = idx>>3, c = idx&7
    uint32_t st[4];
    size_t ga[4], gb[4];
    #pragma unroll
    for (int i = 0; i < 4; ++i) {
        const int idx = i * 256 + tid;
        const int r = idx >> 3, cc = idx & 7;
        st[i] = (uint32_t)(r * 128 + ((cc ^ (r & 7)) << 4));
        ga[i] = (size_t)r * LDA + cc * 8;
        gb[i] = (size_t)r * LDB + cc * 8;
    }

    // ldmatrix lane bases (128B rows). XOR = row&7, invariant across mt/ntp (stride 16).
    const int a_row = wm * 64 + (lane & 15);
    const int a_hi  = (lane >> 4) & 1;
    const int xa    = a_row & 7;
    const uint32_t a_base = (uint32_t)(a_row * 128);
    const int b_row = wn * 32 + (lane & 7) + ((lane & 16) ? 8 : 0);
    const int b_hi  = (lane >> 3) & 1;
    const int xb    = b_row & 7;
    const uint32_t b_base = (uint32_t)(b_row * 128);

    SC_ISSUE_CHUNK(smem_base, 0);

    #pragma unroll 1
    for (int ch = 0; ch < CPS; ++ch) {
        CP_WAIT(0);
        __syncthreads();
        if (ch + 1 < CPS) {
            const uint32_t nb = smem_base + (uint32_t)((ch + 1) & 1) * SC_STAGE_B;
            SC_ISSUE_CHUNK(nb, (ch + 1) * 64);
        }

        const uint32_t bb = smem_base + (uint32_t)(ch & 1) * SC_STAGE_B;
        #pragma unroll
        for (int ks = 0; ks < 4; ++ks) {           // 4 k16 steps per 64-K chunk
            const uint32_t ka  = (uint32_t)(((ks * 2 + a_hi) ^ xa) << 4);
            const uint32_t kb2 = (uint32_t)(((ks * 2 + b_hi) ^ xb) << 4);
            uint32_t ah[4][4], bh[2][4];
            #pragma unroll
            for (int mt = 0; mt < 4; ++mt)
                ldsm_x4(ah[mt], bb + 0u * TILE64_B + a_base + mt * 2048u + ka);
            #pragma unroll
            for (int ntp = 0; ntp < 2; ++ntp)
                ldsm_x4(bh[ntp], bb + 2u * TILE64_B + b_base + ntp * 2048u + kb2);
            #pragma unroll
            for (int mt = 0; mt < 4; ++mt)
                #pragma unroll
                for (int nt = 0; nt < 4; ++nt)
                    hmma16816f(c[mt][nt], ah[mt], &bh[nt >> 1][(nt & 1) * 2]);
            {
                uint32_t al[4][4];
                #pragma unroll
                for (int mt = 0; mt < 4; ++mt)
                    ldsm_x4(al[mt], bb + 1u * TILE64_B + a_base + mt * 2048u + ka);
                #pragma unroll
                for (int mt = 0; mt < 4; ++mt)
                    #pragma unroll
                    for (int nt = 0; nt < 4; ++nt)
                        hmma16816f(c[mt][nt], al[mt], &bh[nt >> 1][(nt & 1) * 2]);
            }
        }
    }
}

// ---------------- GEMM1: S = (Q.K^T) * w[n]/sqrt(D) -> fp16 ----------------------
__global__ __launch_bounds__(256, 2) void scores_mma_kernel() {
    extern __shared__ __half dynsmem_h[];
    __shared__ float s_ws[128];

    const int tid = threadIdx.x, wid = tid >> 5, lane = tid & 31;
    const int grp = lane >> 2, t4 = lane & 3;
    const int wm = wid & 1, wn = wid >> 1;
    const int b = blockIdx.z, m0 = blockIdx.y << 7, n0 = blockIdx.x << 7;

    if (tid < 128) s_ws[tid] = g_w[n0 + tid] * 0.04419417382415922f;

    const size_t boff = (size_t)b * SEQ * DIM;
    const __half* A0 = g_qhi + boff + (size_t)m0 * DIM;
    const __half* A1 = g_qlo + boff + (size_t)m0 * DIM;
    const __half* B0 = g_k16 + boff + (size_t)n0 * DIM;

    float c[4][4][4];
    #pragma unroll
    for (int i = 0; i < 4; ++i)
        #pragma unroll
        for (int j = 0; j < 4; ++j)
            #pragma unroll
            for (int q = 0; q < 4; ++q) c[i][j][q] = 0.f;

    scores_mainloop<DIM, DIM, DIM / 64>(A0, A1, B0, dynsmem_h, c);

    __half* sb = g_sp16 + (size_t)b * SEQ * SEQ;
    #pragma unroll
    for (int mt = 0; mt < 4; ++mt) {
        #pragma unroll
        for (int nt = 0; nt < 4; ++nt) {
            const int col_l = wn * 32 + nt * 8 + t4 * 2;
            const int col = n0 + col_l;
            const float w0 = s_ws[col_l], w1v = s_ws[col_l + 1];
            #pragma unroll
            for (int rr = 0; rr < 2; ++rr) {
                const int row = m0 + wm * 64 + mt * 16 + grp + rr * 8;
                __half2 o = __floats2half2_rn(c[mt][nt][2 * rr] * w0,
                                              c[mt][nt][2 * rr + 1] * w1v);
                *(__half2*)(sb + (size_t)row * SEQ + col) = o;
            }
        }
    }
}

// ---------------- softmax over fp16 scores -> fp16 probs (in place) ---------------
__global__ __launch_bounds__(256) void softmax_kernel2() {
    const size_t row = blockIdx.x;
    __half* p = g_sp16 + row * SEQ;
    const int tid = threadIdx.x, lane = tid & 31, wid = tid >> 5;
    __shared__ float red[8];

    uint4 u = ((const uint4*)p)[tid];
    float x[8];
    const __half2* h2 = (const __half2*)&u;
    #pragma unroll
    for (int q = 0; q < 4; ++q) {
        float2 a = __half22float2(h2[q]);
        x[2 * q]     = a.x;
        x[2 * q + 1] = a.y;
    }

    float m = x[0];
    #pragma unroll
    for (int i = 1; i < 8; ++i) m = fmaxf(m, x[i]);
    m = wredmax(m);
    if (lane == 0) red[wid] = m;
    __syncthreads();
    m = red[0];
    #pragma unroll
    for (int i = 1; i < 8; ++i) m = fmaxf(m, red[i]);
    __syncthreads();

    float e[8], s = 0.f;
    #pragma unroll
    for (int i = 0; i < 8; ++i) { e[i] = __expf(x[i] - m); s += e[i]; }
    s = wredsum(s);
    if (lane == 0) red[wid] = s;
    __syncthreads();
    float tot = 0.f;
    #pragma unroll
    for (int i = 0; i < 8; ++i) tot += red[i];
    const float inv = 1.0f / tot;

    __half2 hh[4];
    #pragma unroll
    for (int q = 0; q < 4; ++q)
        hh[q] = __floats2half2_rn(e[2 * q] * inv, e[2 * q + 1] * inv);
    ((uint4*)p)[tid] = *(uint4*)hh;
}

// =================================================================================
// PV GEMM core: 1-term fp16, K-chunk 64 (two 32-sub-tiles per stage).
// Stage = [A_k0, A_k1, B_k0, B_k1] = 32 KB; 3 stages.
// =================================================================================
#define PV_STAGE_B (4u * TILE_B)        // 32768
#define PV_DSMEM   (3u * PV_STAGE_B)    // 98304

#define PV_ISSUE_CHUNK(bufbase, kb) do { \
    CP_ASYNC16((bufbase) + 0u * TILE_B + st0, aP + g0a + (kb)); \
    CP_ASYNC16((bufbase) + 0u * TILE_B + st1, aP + g1a + (kb)); \
    CP_ASYNC16((bufbase) + 1u * TILE_B + st0, aP + g0a + (kb) + 32); \
    CP_ASYNC16((bufbase) + 1u * TILE_B + st1, aP + g1a + (kb) + 32); \
    CP_ASYNC16((bufbase) + 2u * TILE_B + st0, bV + g0b + (kb)); \
    CP_ASYNC16((bufbase) + 2u * TILE_B + st1, bV + g1b + (kb)); \
    CP_ASYNC16((bufbase) + 3u * TILE_B + st0, bV + g0b + (kb) + 32); \
    CP_ASYNC16((bufbase) + 3u * TILE_B + st1, bV + g1b + (kb) + 32); \
    CP_COMMIT(); \
} while (0)

template <int LDA, int LDB, int CPS>   // CPS = number of 64-K chunks
__device__ __forceinline__ void pv_mainloop(
    const __half* aP, const __half* bV,
    __half* smem, float c[4][4][4])
{
    const int tid = threadIdx.x;
    const int wid = tid >> 5, lane = tid & 31;
    const int wm = wid & 1, wn = wid >> 1;

    const uint32_t smem_base = smem_u32(smem);

    const int r0 = tid >> 2,         c0 = tid & 3;
    const int r1 = (256 + tid) >> 2, c1 = tid & 3;
    const uint32_t st0 = (uint32_t)(r0 * 64 + ((c0 ^ ((r0 >> 1) & 3)) << 4));
    const uint32_t st1 = (uint32_t)(r1 * 64 + ((c1 ^ ((r1 >> 1) & 3)) << 4));
    const size_t g0a = (size_t)r0 * LDA + c0 * 8, g1a = (size_t)r1 * LDA + c1 * 8;
    const size_t g0b = (size_t)r0 * LDB + c0 * 8, g1b = (size_t)r1 * LDB + c1 * 8;

    const int a_row = wm * 64 + (lane & 15);
    const int a_hi  = (lane >> 4) & 1;
    const int xa    = (a_row >> 1) & 3;
    const uint32_t a_base = (uint32_t)(a_row * 64);
    const int b_row = wn * 32 + (lane & 7) + ((lane & 16) ? 8 : 0);
    const int b_hi  = (lane >> 3) & 1;
    const int xb    = (b_row >> 1) & 3;
    const uint32_t b_base = (uint32_t)(b_row * 64);

    PV_ISSUE_CHUNK(smem_base, 0);
    PV_ISSUE_CHUNK(smem_base + PV_STAGE_B, 64);

    #pragma unroll 1
    for (int ch = 0; ch < CPS; ++ch) {
        if (ch + 1 < CPS) { CP_WAIT(1); } else { CP_WAIT(0); }
        __syncthreads();
        if (ch + 2 < CPS) {
            const uint32_t nb = smem_base + (uint32_t)((ch + 2) % 3) * PV_STAGE_B;
            const int kb = (ch + 2) * 64;
            PV_ISSUE_CHUNK(nb, kb);
        }

        const uint32_t bb = smem_base + (uint32_t)(ch % 3) * PV_STAGE_B;
        #pragma unroll
        for (int sub = 0; sub < 2; ++sub) {
            #pragma unroll
            for (int ks = 0; ks < 2; ++ks) {
                const uint32_t ka  = (uint32_t)(((ks * 2 + a_hi) ^ xa) << 4);
                const uint32_t kb2 = (uint32_t)(((ks * 2 + b_hi) ^ xb) << 4);
                uint32_t ah[4][4], bh[2][4];
                #pragma unroll
                for (int mt = 0; mt < 4; ++mt)
                    ldsm_x4(ah[mt], bb + (uint32_t)sub * TILE_B + a_base + mt * 1024u + ka);
                #pragma unroll
                for (int ntp = 0; ntp < 2; ++ntp)
                    ldsm_x4(bh[ntp], bb + (2u + sub) * TILE_B + b_base + ntp * 1024u + kb2);
                #pragma unroll
                for (int mt = 0; mt < 4; ++mt)
                    #pragma unroll
                    for (int nt = 0; nt < 4; ++nt)
                        hmma16816f(c[mt][nt], ah[mt], &bh[nt >> 1][(nt & 1) * 2]);
            }
        }
    }
}

// ---------------- GEMM2 (K-split): part[s] = P[:, ks] . V[ks, :] ------------------
__global__ __launch_bounds__(256, 2) void pv_mma_kernel() {
    extern __shared__ __half dynsmem_h[];

    const int tid = threadIdx.x, wid = tid >> 5, lane = tid & 31;
    const int grp = lane >> 2, t4 = lane & 3;
    const int wm = wid & 1, wn = wid >> 1;
    const int b = blockIdx.z >> 1, s = blockIdx.z & 1;
    const int m0 = blockIdx.y << 7, n0 = blockIdx.x << 7;
    const int k0 = s * (SEQ / KSPLIT);

    const __half* A0 = g_sp16 + (size_t)b * SEQ * SEQ + (size_t)m0 * SEQ + k0;
    const __half* B0 = g_vt16 + (size_t)b * DIM * SEQ + (size_t)n0 * SEQ + k0;

    float c[4][4][4];
    #pragma unroll
    for (int i = 0; i < 4; ++i)
        #pragma unroll
        for (int j = 0; j < 4; ++j)
            #pragma unroll
            for (int q = 0; q < 4; ++q) c[i][j][q] = 0.f;

    pv_mainloop<SEQ, SEQ, (SEQ / KSPLIT) / 64>(A0, B0, dynsmem_h, c);

    float* pout = g_part[s] + (size_t)b * SEQ * DIM;
    #pragma unroll
    for (int mt = 0; mt < 4; ++mt) {
        #pragma unroll
        for (int nt = 0; nt < 4; ++nt) {
            const int col = n0 + wn * 32 + nt * 8 + t4 * 2;
            #pragma unroll
            for (int rr = 0; rr < 2; ++rr) {
                const int row = m0 + wm * 64 + mt * 16 + grp + rr * 8;
                float2 o = make_float2(c[mt][nt][2 * rr], c[mt][nt][2 * rr + 1]);
                *(float2*)(pout + (size_t)row * DIM + col) = o;
            }
        }
    }
}

// ---------------- reduce: out = blend * sum(parts) + (1-blend) * meanV -----------
__global__ __launch_bounds__(256) void reduce_kernel(float* __restrict__ out) {
    const size_t i4 = (size_t)blockIdx.x * 256 + threadIdx.x;   // float4 index
    const float blend = g_blend;
    const float ob = 1.0f - blend;
    const size_t ei = i4 * 4;
    const int b = (int)(ei / ((size_t)SEQ * DIM));
    const int d = (int)(ei % DIM);

    float4 p0 = ((const float4*)g_part[0])[i4];
    float4 p1 = ((const float4*)g_part[1])[i4];
    const float* mv = g_meanV + b * DIM + d;

    float4 o;
    o.x = fmaf(blend, p0.x + p1.x, ob * mv[0]);
    o.y = fmaf(blend, p0.y + p1.y, ob * mv[1]);
    o.z = fmaf(blend, p0.z + p1.z, ob * mv[2]);
    o.w = fmaf(blend, p0.w + p1.w, ob * mv[3]);
    ((float4*)out)[i4] = o;
}

// ---------------- launch -----------------------------------------------------------
extern "C" void kernel_launch(void* const* d_in, const int* in_sizes, int n_in,
                              void* d_out, int out_size) {
    const float* q  = (const float*)d_in[0];
    const float* k  = (const float*)d_in[1];
    const float* v  = (const float*)d_in[2];
    const float* ps = (const float*)d_in[3];
    const float* pb = (const float*)d_in[4];
    const float* w1 = (const float*)d_in[5];
    const float* b1 = (const float*)d_in[6];
    const float* w2 = (const float*)d_in[7];
    const float* b2 = (const float*)d_in[8];
    float* out = (float*)d_out;

    static bool attr_set = false;
    if (!attr_set) {
        cudaFuncSetAttribute(scores_mma_kernel,
                             cudaFuncAttributeMaxDynamicSharedMemorySize, SC_DSMEM);
        cudaFuncSetAttribute(pv_mma_kernel,
                             cudaFuncAttributeMaxDynamicSharedMemorySize, PV_DSMEM);
        attr_set = true;
    }

    prep_kernel<<<1, 1024>>>(ps, pb, w1, b1, w2, b2);
    splitqk_kernel<<<dim3((BATCH * SEQ * DIM / 4) / 256, 2), 256>>>(q, k);
    splitv_kernel<<<dim3(SEQ / 32, DIM / 32, BATCH), dim3(32, 8)>>>(v);
    scores_mma_kernel<<<dim3(SEQ / 128, SEQ / 128, BATCH), 256, SC_DSMEM>>>();
    meanv_kernel<<<dim3(DIM / 128, BATCH), 128>>>(v);
    softmax_kernel2<<<BATCH * SEQ, 256>>>();
    pv_mma_kernel<<<dim3(DIM / 128, SEQ / 128, BATCH * KSPLIT), 256, PV_DSMEM>>>();
    reduce_kernel<<<(BATCH * SEQ * DIM / 4) / 256, 256>>>(out);
}

// round 15
// speedup vs baseline: 1.7721x; 1.0500x over previous
#include <cuda_runtime.h>
#include <cuda_bf16.h>
#include <cuda_fp16.h>
#include <math.h>
#include <stdint.h>

#define BATCH 8
#define SEQ   2048
#define DIM   512
#define ITERS 12

typedef __nv_bfloat16 bf16;

// ---------------- scratch (static device memory; no allocations) --------------
__device__ __half g_qhi[(size_t)BATCH * SEQ * DIM];   // Q fp16 hi
__device__ __half g_qlo[(size_t)BATCH * SEQ * DIM];   // Q fp16 lo
__device__ __half g_k16[(size_t)BATCH * SEQ * DIM];   // K fp16 single
__device__ __half g_vt16[(size_t)BATCH * DIM * SEQ];  // V^T fp16 single
__device__ __half g_sp16[(size_t)BATCH * SEQ * SEQ];  // scores -> probs (fp16, in place)
__device__ float g_w[SEQ];
__device__ float g_blend;
__device__ float g_meanV[BATCH * DIM];
__device__ float g_pa[4096];
__device__ float g_pb[4096];

// ---------------- helpers ----------------------------------------------------
__device__ __forceinline__ uint32_t smem_u32(const void* p) {
    uint32_t a;
    asm("{ .reg .u64 t; cvta.to.shared.u64 t, %1; cvt.u32.u64 %0, t; }" : "=r"(a) : "l"(p));
    return a;
}
__device__ __forceinline__ void hmma16816f(float c[4], const uint32_t a[4], const uint32_t b[2]) {
    asm volatile(
        "mma.sync.aligned.m16n8k16.row.col.f32.f16.f16.f32 "
        "{%0,%1,%2,%3}, {%4,%5,%6,%7}, {%8,%9}, {%0,%1,%2,%3};"
        : "+f"(c[0]), "+f"(c[1]), "+f"(c[2]), "+f"(c[3])
        : "r"(a[0]), "r"(a[1]), "r"(a[2]), "r"(a[3]), "r"(b[0]), "r"(b[1]));
}
__device__ __forceinline__ void ldsm_x4(uint32_t r[4], uint32_t addr) {
    asm volatile("ldmatrix.sync.aligned.m8n8.x4.shared.b16 {%0,%1,%2,%3}, [%4];"
                 : "=r"(r[0]), "=r"(r[1]), "=r"(r[2]), "=r"(r[3]) : "r"(addr));
}
#define CP_ASYNC16(saddr, gptr) \
    asm volatile("cp.async.cg.shared.global [%0], [%1], 16;" :: "r"(saddr), "l"(gptr))
#define CP_COMMIT() asm volatile("cp.async.commit_group;" ::: "memory")
#define CP_WAIT(n)  asm volatile("cp.async.wait_group %0;" :: "n"(n) : "memory")

__device__ __forceinline__ float wredmax(float v) {
    #pragma unroll
    for (int o = 16; o > 0; o >>= 1) v = fmaxf(v, __shfl_xor_sync(0xffffffffu, v, o));
    return v;
}
__device__ __forceinline__ float wredmin(float v) {
    #pragma unroll
    for (int o = 16; o > 0; o >>= 1) v = fminf(v, __shfl_xor_sync(0xffffffffu, v, o));
    return v;
}
__device__ __forceinline__ float wredsum(float v) {
    #pragma unroll
    for (int o = 16; o > 0; o >>= 1) v += __shfl_xor_sync(0xffffffffu, v, o);
    return v;
}

// ---------------- prep: dragon pattern + softplus weights + blend scalar ------
__global__ void prep_kernel(const float* __restrict__ ps, const float* __restrict__ pb,
                            const float* __restrict__ w1, const float* __restrict__ b1,
                            const float* __restrict__ w2, const float* __restrict__ b2) {
    const int tid = threadIdx.x, nt = blockDim.x;
    const int lane = tid & 31, wid = tid >> 5;
    __shared__ float redmn[32], redmx[32];
    __shared__ float s_mn, s_mx;
    const int it = 11;

    float* cur = g_pa;
    float* tmp = g_pb;
    if (tid == 0) cur[0] = 0.5f;
    __syncthreads();

    int len = 1;
    const float k3 = 1.0f / 3.0f;
    for (int iter = 1; iter < ITERS; ++iter) {
        const int nl = 2 * len + 1;
        for (int j = tid; j < nl; j += nt) {
            float val;
            if (j < len)       val = cur[j];
            else if (j == len) val = 0.5f;
            else               val = 1.0f - cur[nl - 1 - j];
            tmp[j] = val;
        }
        __syncthreads();
        float lmn = 3.4e38f, lmx = -3.4e38f;
        for (int j = tid; j < nl; j += nt) {
            float l = (j > 0)      ? tmp[j - 1] : 0.0f;
            float c = tmp[j];
            float r = (j + 1 < nl) ? tmp[j + 1] : 0.0f;
            float val = l * k3 + c * k3 + r * k3;
            cur[j] = val;
            lmn = fminf(lmn, val);
            lmx = fmaxf(lmx, val);
        }
        lmn = wredmin(lmn);
        lmx = wredmax(lmx);
        if (lane == 0) { redmn[wid] = lmn; redmx[wid] = lmx; }
        __syncthreads();
        if (wid == 0) {
            float a = (lane < nt / 32) ? redmn[lane] : 3.4e38f;
            float c = (lane < nt / 32) ? redmx[lane] : -3.4e38f;
            a = wredmin(a);
            c = wredmax(c);
            if (lane == 0) { s_mn = a; s_mx = c; }
        }
        __syncthreads();
        const float mn = s_mn, mx = s_mx;
        for (int j = tid; j < nl; j += nt)
            cur[j] = (cur[j] - mn) / (mx - mn + 1e-8f);
        __syncthreads();
        len = nl;
    }

    const float sc = ps[it], bi = pb[it];
    for (int s = tid; s < SEQ; s += nt) {
        double x = (double)s / (double)(SEQ - 1);
        double t = x * (double)(len - 1);
        int i0 = (int)t;
        if (i0 > len - 2) i0 = len - 2;
        double fr = t - (double)i0;
        float w = (float)((1.0 - fr) * (double)cur[i0] + fr * (double)cur[i0 + 1]);
        float z = fmaf(w, sc, bi);
        g_w[s] = fmaxf(z, 0.0f) + log1pf(expf(-fabsf(z)));
    }

    if (tid == 0) {
        float acc = b2[0];
        for (int j = 0; j < 64; ++j) {
            float h = w1[it * 64 + j] + b1[j];
            if (h > 0.0f) acc = fmaf(h, w2[j], acc);
        }
        g_blend = 1.0f / (1.0f + expf(-acc));
    }
}

// ---------------- column mean of V per batch -----------------------------------
__global__ void meanv_kernel(const float* __restrict__ V) {
    const int b = blockIdx.y;
    const int d = (blockIdx.x << 7) + threadIdx.x;
    const float* p = V + (size_t)b * SEQ * DIM + d;
    float a0 = 0.f, a1 = 0.f, a2 = 0.f, a3 = 0.f;
    #pragma unroll 4
    for (int k = 0; k < SEQ; k += 4) {
        a0 += p[(size_t)(k + 0) * DIM];
        a1 += p[(size_t)(k + 1) * DIM];
        a2 += p[(size_t)(k + 2) * DIM];
        a3 += p[(size_t)(k + 3) * DIM];
    }
    g_meanV[b * DIM + d] = (a0 + a1 + a2 + a3) * (1.0f / SEQ);
}

// ---------------- split Q (fp16 hi/lo) and K (fp16 single) -----------------------
__global__ __launch_bounds__(256) void splitqk_kernel(const float* __restrict__ Q,
                                                      const float* __restrict__ K) {
    const size_t i = (size_t)blockIdx.x * 256 + threadIdx.x;
    if (blockIdx.y == 0) {
        float4 v = ((const float4*)Q)[i];
        __half h0 = __float2half_rn(v.x), h1 = __float2half_rn(v.y);
        __half h2 = __float2half_rn(v.z), h3 = __float2half_rn(v.w);
        __half2 hh[2] = {__halves2half2(h0, h1), __halves2half2(h2, h3)};
        __half2 ll[2] = {
            __floats2half2_rn(v.x - __half2float(h0), v.y - __half2float(h1)),
            __floats2half2_rn(v.z - __half2float(h2), v.w - __half2float(h3))};
        ((uint2*)g_qhi)[i] = *(uint2*)hh;
        ((uint2*)g_qlo)[i] = *(uint2*)ll;
    } else {
        float4 v = ((const float4*)K)[i];
        __half2 kk[2] = {__floats2half2_rn(v.x, v.y), __floats2half2_rn(v.z, v.w)};
        ((uint2*)g_k16)[i] = *(uint2*)kk;
    }
}

// ---------------- transpose V: Vt[b][d][s] fp16 single ---------------------------
__global__ void splitv_kernel(const float* __restrict__ V) {
    __shared__ float t[32][33];
    const int b = blockIdx.z;
    const int s0 = blockIdx.x << 5, d0 = blockIdx.y << 5;
    const int tx = threadIdx.x, ty = threadIdx.y;
    const float* src = V + ((size_t)b * SEQ + s0) * DIM + d0 + tx;
    #pragma unroll
    for (int i = 0; i < 32; i += 8) t[ty + i][tx] = src[(size_t)(ty + i) * DIM];
    __syncthreads();
    #pragma unroll
    for (int i = 0; i < 32; i += 8) {
        float x = t[tx][ty + i];
        size_t o = ((size_t)b * DIM + d0 + ty + i) * SEQ + s0 + tx;
        g_vt16[o] = __float2half_rn(x);
    }
}

#define TILE_B   8192u               // bytes per 128x32 16-bit tile
#define TILE64_B 16384u              // bytes per 128x64 16-bit tile

// =================================================================================
// Scores GEMM core: 2-term fp16, K-chunk 64, 128B swizzled rows (c ^= row&7).
// 256 threads, 2x4 warp grid, warp tile 64x32.
// Stage = [Ahi, Alo, K] = 48 KB; 2 stages (96 KB); one barrier per 64-K chunk.
// =================================================================================
#define SC_STAGE_B (3u * TILE64_B)      // 49152
#define SC_DSMEM   (2u * SC_STAGE_B)    // 98304

#define SC_ISSUE_CHUNK(bufbase, kb) do { \
    _Pragma("unroll") \
    for (int i = 0; i < 4; ++i) { \
        CP_ASYNC16((bufbase) + 0u * TILE64_B + st[i], aHi + ga[i] + (kb)); \
        CP_ASYNC16((bufbase) + 1u * TILE64_B + st[i], aLo + ga[i] + (kb)); \
        CP_ASYNC16((bufbase) + 2u * TILE64_B + st[i], bK + gb[i] + (kb)); \
    } \
    CP_COMMIT(); \
} while (0)

template <int LDA, int LDB, int CPS>   // CPS = number of 64-K chunks
__device__ __forceinline__ void scores_mainloop(
    const __half* aHi, const __half* aLo, const __half* bK,
    __half* smem, float c[4][4][4])
{
    const int tid = threadIdx.x;
    const int wid = tid >> 5, lane = tid & 31;
    const int wm = wid & 1, wn = wid >> 1;

    const uint32_t smem_base = smem_u32(smem);

    uint32_t st[4];
    size_t ga[4], gb[4];
    #pragma unroll
    for (int i = 0; i < 4; ++i) {
        const int idx = i * 256 + tid;
        const int r = idx >> 3, cc = idx & 7;
        st[i] = (uint32_t)(r * 128 + ((cc ^ (r & 7)) << 4));
        ga[i] = (size_t)r * LDA + cc * 8;
        gb[i] = (size_t)r * LDB + cc * 8;
    }

    const int a_row = wm * 64 + (lane & 15);
    const int a_hi  = (lane >> 4) & 1;
    const int xa    = a_row & 7;
    const uint32_t a_base = (uint32_t)(a_row * 128);
    const int b_row = wn * 32 + (lane & 7) + ((lane & 16) ? 8 : 0);
    const int b_hi  = (lane >> 3) & 1;
    const int xb    = b_row & 7;
    const uint32_t b_base = (uint32_t)(b_row * 128);

    SC_ISSUE_CHUNK(smem_base, 0);

    #pragma unroll 1
    for (int ch = 0; ch < CPS; ++ch) {
        CP_WAIT(0);
        __syncthreads();
        if (ch + 1 < CPS) {
            const uint32_t nb = smem_base + (uint32_t)((ch + 1) & 1) * SC_STAGE_B;
            SC_ISSUE_CHUNK(nb, (ch + 1) * 64);
        }

        const uint32_t bb = smem_base + (uint32_t)(ch & 1) * SC_STAGE_B;
        #pragma unroll
        for (int ks = 0; ks < 4; ++ks) {
            const uint32_t ka  = (uint32_t)(((ks * 2 + a_hi) ^ xa) << 4);
            const uint32_t kb2 = (uint32_t)(((ks * 2 + b_hi) ^ xb) << 4);
            uint32_t ah[4][4], bh[2][4];
            #pragma unroll
            for (int mt = 0; mt < 4; ++mt)
                ldsm_x4(ah[mt], bb + 0u * TILE64_B + a_base + mt * 2048u + ka);
            #pragma unroll
            for (int ntp = 0; ntp < 2; ++ntp)
                ldsm_x4(bh[ntp], bb + 2u * TILE64_B + b_base + ntp * 2048u + kb2);
            #pragma unroll
            for (int mt = 0; mt < 4; ++mt)
                #pragma unroll
                for (int nt = 0; nt < 4; ++nt)
                    hmma16816f(c[mt][nt], ah[mt], &bh[nt >> 1][(nt & 1) * 2]);
            {
                uint32_t al[4][4];
                #pragma unroll
                for (int mt = 0; mt < 4; ++mt)
                    ldsm_x4(al[mt], bb + 1u * TILE64_B + a_base + mt * 2048u + ka);
                #pragma unroll
                for (int mt = 0; mt < 4; ++mt)
                    #pragma unroll
                    for (int nt = 0; nt < 4; ++nt)
                        hmma16816f(c[mt][nt], al[mt], &bh[nt >> 1][(nt & 1) * 2]);
            }
        }
    }
}

// ---------------- GEMM1: S = (Q.K^T) * w[n]/sqrt(D) -> fp16 ----------------------
__global__ __launch_bounds__(256, 2) void scores_mma_kernel() {
    extern __shared__ __half dynsmem_h[];
    __shared__ float s_ws[128];

    const int tid = threadIdx.x, wid = tid >> 5, lane = tid & 31;
    const int grp = lane >> 2, t4 = lane & 3;
    const int wm = wid & 1, wn = wid >> 1;
    const int b = blockIdx.z, m0 = blockIdx.y << 7, n0 = blockIdx.x << 7;

    if (tid < 128) s_ws[tid] = g_w[n0 + tid] * 0.04419417382415922f;

    const size_t boff = (size_t)b * SEQ * DIM;
    const __half* A0 = g_qhi + boff + (size_t)m0 * DIM;
    const __half* A1 = g_qlo + boff + (size_t)m0 * DIM;
    const __half* B0 = g_k16 + boff + (size_t)n0 * DIM;

    float c[4][4][4];
    #pragma unroll
    for (int i = 0; i < 4; ++i)
        #pragma unroll
        for (int j = 0; j < 4; ++j)
            #pragma unroll
            for (int q = 0; q < 4; ++q) c[i][j][q] = 0.f;

    scores_mainloop<DIM, DIM, DIM / 64>(A0, A1, B0, dynsmem_h, c);

    __half* sb = g_sp16 + (size_t)b * SEQ * SEQ;
    #pragma unroll
    for (int mt = 0; mt < 4; ++mt) {
        #pragma unroll
        for (int nt = 0; nt < 4; ++nt) {
            const int col_l = wn * 32 + nt * 8 + t4 * 2;
            const int col = n0 + col_l;
            const float w0 = s_ws[col_l], w1v = s_ws[col_l + 1];
            #pragma unroll
            for (int rr = 0; rr < 2; ++rr) {
                const int row = m0 + wm * 64 + mt * 16 + grp + rr * 8;
                __half2 o = __floats2half2_rn(c[mt][nt][2 * rr] * w0,
                                              c[mt][nt][2 * rr + 1] * w1v);
                *(__half2*)(sb + (size_t)row * SEQ + col) = o;
            }
        }
    }
}

// ---------------- softmax over fp16 scores -> fp16 probs (in place) ---------------
__global__ __launch_bounds__(256) void softmax_kernel2() {
    const size_t row = blockIdx.x;
    __half* p = g_sp16 + row * SEQ;
    const int tid = threadIdx.x, lane = tid & 31, wid = tid >> 5;
    __shared__ float red[8];

    uint4 u = ((const uint4*)p)[tid];
    float x[8];
    const __half2* h2 = (const __half2*)&u;
    #pragma unroll
    for (int q = 0; q < 4; ++q) {
        float2 a = __half22float2(h2[q]);
        x[2 * q]     = a.x;
        x[2 * q + 1] = a.y;
    }

    float m = x[0];
    #pragma unroll
    for (int i = 1; i < 8; ++i) m = fmaxf(m, x[i]);
    m = wredmax(m);
    if (lane == 0) red[wid] = m;
    __syncthreads();
    m = red[0];
    #pragma unroll
    for (int i = 1; i < 8; ++i) m = fmaxf(m, red[i]);
    __syncthreads();

    float e[8], s = 0.f;
    #pragma unroll
    for (int i = 0; i < 8; ++i) { e[i] = __expf(x[i] - m); s += e[i]; }
    s = wredsum(s);
    if (lane == 0) red[wid] = s;
    __syncthreads();
    float tot = 0.f;
    #pragma unroll
    for (int i = 0; i < 8; ++i) tot += red[i];
    const float inv = 1.0f / tot;

    __half2 hh[4];
    #pragma unroll
    for (int q = 0; q < 4; ++q)
        hh[q] = __floats2half2_rn(e[2 * q] * inv, e[2 * q + 1] * inv);
    ((uint4*)p)[tid] = *(uint4*)hh;
}

// =================================================================================
// PV GEMM core: 1-term fp16, K-chunk 64 (two 32-sub-tiles per stage).
// Stage = [A_k0, A_k1, B_k0, B_k1] = 32 KB; 3 stages. Full K = 2048 (no split).
// =================================================================================
#define PV_STAGE_B (4u * TILE_B)        // 32768
#define PV_DSMEM   (3u * PV_STAGE_B)    // 98304

#define PV_ISSUE_CHUNK(bufbase, kb) do { \
    CP_ASYNC16((bufbase) + 0u * TILE_B + st0, aP + g0a + (kb)); \
    CP_ASYNC16((bufbase) + 0u * TILE_B + st1, aP + g1a + (kb)); \
    CP_ASYNC16((bufbase) + 1u * TILE_B + st0, aP + g0a + (kb) + 32); \
    CP_ASYNC16((bufbase) + 1u * TILE_B + st1, aP + g1a + (kb) + 32); \
    CP_ASYNC16((bufbase) + 2u * TILE_B + st0, bV + g0b + (kb)); \
    CP_ASYNC16((bufbase) + 2u * TILE_B + st1, bV + g1b + (kb)); \
    CP_ASYNC16((bufbase) + 3u * TILE_B + st0, bV + g0b + (kb) + 32); \
    CP_ASYNC16((bufbase) + 3u * TILE_B + st1, bV + g1b + (kb) + 32); \
    CP_COMMIT(); \
} while (0)

template <int LDA, int LDB, int CPS>   // CPS = number of 64-K chunks
__device__ __forceinline__ void pv_mainloop(
    const __half* aP, const __half* bV,
    __half* smem, float c[4][4][4])
{
    const int tid = threadIdx.x;
    const int wid = tid >> 5, lane = tid & 31;
    const int wm = wid & 1, wn = wid >> 1;

    const uint32_t smem_base = smem_u32(smem);

    const int r0 = tid >> 2,         c0 = tid & 3;
    const int r1 = (256 + tid) >> 2, c1 = tid & 3;
    const uint32_t st0 = (uint32_t)(r0 * 64 + ((c0 ^ ((r0 >> 1) & 3)) << 4));
    const uint32_t st1 = (uint32_t)(r1 * 64 + ((c1 ^ ((r1 >> 1) & 3)) << 4));
    const size_t g0a = (size_t)r0 * LDA + c0 * 8, g1a = (size_t)r1 * LDA + c1 * 8;
    const size_t g0b = (size_t)r0 * LDB + c0 * 8, g1b = (size_t)r1 * LDB + c1 * 8;

    const int a_row = wm * 64 + (lane & 15);
    const int a_hi  = (lane >> 4) & 1;
    const int xa    = (a_row >> 1) & 3;
    const uint32_t a_base = (uint32_t)(a_row * 64);
    const int b_row = wn * 32 + (lane & 7) + ((lane & 16) ? 8 : 0);
    const int b_hi  = (lane >> 3) & 1;
    const int xb    = (b_row >> 1) & 3;
    const uint32_t b_base = (uint32_t)(b_row * 64);

    PV_ISSUE_CHUNK(smem_base, 0);
    PV_ISSUE_CHUNK(smem_base + PV_STAGE_B, 64);

    #pragma unroll 1
    for (int ch = 0; ch < CPS; ++ch) {
        if (ch + 1 < CPS) { CP_WAIT(1); } else { CP_WAIT(0); }
        __syncthreads();
        if (ch + 2 < CPS) {
            const uint32_t nb = smem_base + (uint32_t)((ch + 2) % 3) * PV_STAGE_B;
            const int kb = (ch + 2) * 64;
            PV_ISSUE_CHUNK(nb, kb);
        }

        const uint32_t bb = smem_base + (uint32_t)(ch % 3) * PV_STAGE_B;
        #pragma unroll
        for (int sub = 0; sub < 2; ++sub) {
            #pragma unroll
            for (int ks = 0; ks < 2; ++ks) {
                const uint32_t ka  = (uint32_t)(((ks * 2 + a_hi) ^ xa) << 4);
                const uint32_t kb2 = (uint32_t)(((ks * 2 + b_hi) ^ xb) << 4);
                uint32_t ah[4][4], bh[2][4];
                #pragma unroll
                for (int mt = 0; mt < 4; ++mt)
                    ldsm_x4(ah[mt], bb + (uint32_t)sub * TILE_B + a_base + mt * 1024u + ka);
                #pragma unroll
                for (int ntp = 0; ntp < 2; ++ntp)
                    ldsm_x4(bh[ntp], bb + (2u + sub) * TILE_B + b_base + ntp * 1024u + kb2);
                #pragma unroll
                for (int mt = 0; mt < 4; ++mt)
                    #pragma unroll
                    for (int nt = 0; nt < 4; ++nt)
                        hmma16816f(c[mt][nt], ah[mt], &bh[nt >> 1][(nt & 1) * 2]);
            }
        }
    }
}

// ---------------- GEMM2: out = blend * (P.V) + (1-blend) * meanV -----------------
__global__ __launch_bounds__(256, 2) void pv_mma_kernel(float* __restrict__ out) {
    extern __shared__ __half dynsmem_h[];
    __shared__ float s_mv[128];
    __shared__ float s_bl;

    const int tid = threadIdx.x, wid = tid >> 5, lane = tid & 31;
    const int grp = lane >> 2, t4 = lane & 3;
    const int wm = wid & 1, wn = wid >> 1;
    const int b = blockIdx.z;
    const int m0 = blockIdx.y << 7, n0 = blockIdx.x << 7;

    if (tid == 0) s_bl = g_blend;
    __syncthreads();
    const float blend = s_bl;
    if (tid < 128) s_mv[tid] = (1.0f - blend) * g_meanV[b * DIM + n0 + tid];

    const __half* A0 = g_sp16 + (size_t)b * SEQ * SEQ + (size_t)m0 * SEQ;
    const __half* B0 = g_vt16 + (size_t)b * DIM * SEQ + (size_t)n0 * SEQ;

    float c[4][4][4];
    #pragma unroll
    for (int i = 0; i < 4; ++i)
        #pragma unroll
        for (int j = 0; j < 4; ++j)
            #pragma unroll
            for (int q = 0; q < 4; ++q) c[i][j][q] = 0.f;

    pv_mainloop<SEQ, SEQ, SEQ / 64>(A0, B0, dynsmem_h, c);

    #pragma unroll
    for (int mt = 0; mt < 4; ++mt) {
        #pragma unroll
        for (int nt = 0; nt < 4; ++nt) {
            const int col_l = wn * 32 + nt * 8 + t4 * 2;
            const int col = n0 + col_l;
            #pragma unroll
            for (int rr = 0; rr < 2; ++rr) {
                const int row = m0 + wm * 64 + mt * 16 + grp + rr * 8;
                float2 o;
                o.x = fmaf(blend, c[mt][nt][2 * rr],     s_mv[col_l]);
                o.y = fmaf(blend, c[mt][nt][2 * rr + 1], s_mv[col_l + 1]);
                *(float2*)(out + ((size_t)b * SEQ + row) * DIM + col) = o;
            }
        }
    }
}

// ---------------- launch -----------------------------------------------------------
extern "C" void kernel_launch(void* const* d_in, const int* in_sizes, int n_in,
                              void* d_out, int out_size) {
    const float* q  = (const float*)d_in[0];
    const float* k  = (const float*)d_in[1];
    const float* v  = (const float*)d_in[2];
    const float* ps = (const float*)d_in[3];
    const float* pb = (const float*)d_in[4];
    const float* w1 = (const float*)d_in[5];
    const float* b1 = (const float*)d_in[6];
    const float* w2 = (const float*)d_in[7];
    const float* b2 = (const float*)d_in[8];
    float* out = (float*)d_out;

    static bool init_done = false;
    static cudaStream_t s_aux;
    static cudaEvent_t ev_fork, ev_prep, ev_aux;
    if (!init_done) {
        cudaFuncSetAttribute(scores_mma_kernel,
                             cudaFuncAttributeMaxDynamicSharedMemorySize, SC_DSMEM);
        cudaFuncSetAttribute(pv_mma_kernel,
                             cudaFuncAttributeMaxDynamicSharedMemorySize, PV_DSMEM);
        cudaStreamCreateWithFlags(&s_aux, cudaStreamNonBlocking);
        cudaEventCreateWithFlags(&ev_fork, cudaEventDisableTiming);
        cudaEventCreateWithFlags(&ev_prep, cudaEventDisableTiming);
        cudaEventCreateWithFlags(&ev_aux, cudaEventDisableTiming);
        init_done = true;
    }

    // Fork: aux stream handles prep / splitv / meanv concurrently with splitqk.
    cudaEventRecord(ev_fork, 0);
    cudaStreamWaitEvent(s_aux, ev_fork, 0);
    prep_kernel<<<1, 1024, 0, s_aux>>>(ps, pb, w1, b1, w2, b2);
    cudaEventRecord(ev_prep, s_aux);
    splitv_kernel<<<dim3(SEQ / 32, DIM / 32, BATCH), dim3(32, 8), 0, s_aux>>>(v);
    meanv_kernel<<<dim3(DIM / 128, BATCH), 128, 0, s_aux>>>(v);
    cudaEventRecord(ev_aux, s_aux);

    // Main stream
    splitqk_kernel<<<dim3((BATCH * SEQ * DIM / 4) / 256, 2), 256>>>(q, k);
    cudaStreamWaitEvent(0, ev_prep, 0);   // scores epilogue needs g_w
    scores_mma_kernel<<<dim3(SEQ / 128, SEQ / 128, BATCH), 256, SC_DSMEM>>>();
    softmax_kernel2<<<BATCH * SEQ, 256>>>();
    cudaStreamWaitEvent(0, ev_aux, 0);    // pv needs g_vt16, g_meanV, g_blend
    pv_mma_kernel<<<dim3(DIM / 128, SEQ / 128, BATCH), 256, PV_DSMEM>>>(out);
}

// round 16
// speedup vs baseline: 1.7759x; 1.0022x over previous
#include <cuda_runtime.h>
#include <cuda_bf16.h>
#include <cuda_fp16.h>
#include <math.h>
#include <stdint.h>

#define BATCH 8
#define SEQ   2048
#define DIM   512
#define ITERS 12

typedef __nv_bfloat16 bf16;

// ---------------- scratch (static device memory; no allocations) --------------
__device__ __half g_qhi[(size_t)BATCH * SEQ * DIM];   // Q fp16 hi
__device__ __half g_qlo[(size_t)BATCH * SEQ * DIM];   // Q fp16 lo
__device__ __half g_k16[(size_t)BATCH * SEQ * DIM];   // K fp16 single
__device__ __half g_vt16[(size_t)BATCH * DIM * SEQ];  // V^T fp16 single
__device__ __half g_sp16[(size_t)BATCH * SEQ * SEQ];  // U = exp(S) (fp16, unnormalized)
__device__ float g_rowpart[16][(size_t)BATCH * SEQ];  // per-n0-block row sums of U
__device__ float g_rowinv[(size_t)BATCH * SEQ];       // 1 / Z per row
__device__ float g_w[SEQ];
__device__ float g_blend;
__device__ float g_meanV[BATCH * DIM];
__device__ float g_pa[4096];
__device__ float g_pb[4096];

// ---------------- helpers ----------------------------------------------------
__device__ __forceinline__ uint32_t smem_u32(const void* p) {
    uint32_t a;
    asm("{ .reg .u64 t; cvta.to.shared.u64 t, %1; cvt.u32.u64 %0, t; }" : "=r"(a) : "l"(p));
    return a;
}
__device__ __forceinline__ void hmma16816f(float c[4], const uint32_t a[4], const uint32_t b[2]) {
    asm volatile(
        "mma.sync.aligned.m16n8k16.row.col.f32.f16.f16.f32 "
        "{%0,%1,%2,%3}, {%4,%5,%6,%7}, {%8,%9}, {%0,%1,%2,%3};"
        : "+f"(c[0]), "+f"(c[1]), "+f"(c[2]), "+f"(c[3])
        : "r"(a[0]), "r"(a[1]), "r"(a[2]), "r"(a[3]), "r"(b[0]), "r"(b[1]));
}
__device__ __forceinline__ void ldsm_x4(uint32_t r[4], uint32_t addr) {
    asm volatile("ldmatrix.sync.aligned.m8n8.x4.shared.b16 {%0,%1,%2,%3}, [%4];"
                 : "=r"(r[0]), "=r"(r[1]), "=r"(r[2]), "=r"(r[3]) : "r"(addr));
}
#define CP_ASYNC16(saddr, gptr) \
    asm volatile("cp.async.cg.shared.global [%0], [%1], 16;" :: "r"(saddr), "l"(gptr))
#define CP_COMMIT() asm volatile("cp.async.commit_group;" ::: "memory")
#define CP_WAIT(n)  asm volatile("cp.async.wait_group %0;" :: "n"(n) : "memory")

__device__ __forceinline__ float wredmax(float v) {
    #pragma unroll
    for (int o = 16; o > 0; o >>= 1) v = fmaxf(v, __shfl_xor_sync(0xffffffffu, v, o));
    return v;
}
__device__ __forceinline__ float wredmin(float v) {
    #pragma unroll
    for (int o = 16; o > 0; o >>= 1) v = fminf(v, __shfl_xor_sync(0xffffffffu, v, o));
    return v;
}
__device__ __forceinline__ float wredsum(float v) {
    #pragma unroll
    for (int o = 16; o > 0; o >>= 1) v += __shfl_xor_sync(0xffffffffu, v, o);
    return v;
}

// ---------------- prep: dragon pattern + softplus weights + blend scalar ------
__global__ void prep_kernel(const float* __restrict__ ps, const float* __restrict__ pb,
                            const float* __restrict__ w1, const float* __restrict__ b1,
                            const float* __restrict__ w2, const float* __restrict__ b2) {
    const int tid = threadIdx.x, nt = blockDim.x;
    const int lane = tid & 31, wid = tid >> 5;
    __shared__ float redmn[32], redmx[32];
    __shared__ float s_mn, s_mx;
    const int it = 11;

    float* cur = g_pa;
    float* tmp = g_pb;
    if (tid == 0) cur[0] = 0.5f;
    __syncthreads();

    int len = 1;
    const float k3 = 1.0f / 3.0f;
    for (int iter = 1; iter < ITERS; ++iter) {
        const int nl = 2 * len + 1;
        for (int j = tid; j < nl; j += nt) {
            float val;
            if (j < len)       val = cur[j];
            else if (j == len) val = 0.5f;
            else               val = 1.0f - cur[nl - 1 - j];
            tmp[j] = val;
        }
        __syncthreads();
        float lmn = 3.4e38f, lmx = -3.4e38f;
        for (int j = tid; j < nl; j += nt) {
            float l = (j > 0)      ? tmp[j - 1] : 0.0f;
            float c = tmp[j];
            float r = (j + 1 < nl) ? tmp[j + 1] : 0.0f;
            float val = l * k3 + c * k3 + r * k3;
            cur[j] = val;
            lmn = fminf(lmn, val);
            lmx = fmaxf(lmx, val);
        }
        lmn = wredmin(lmn);
        lmx = wredmax(lmx);
        if (lane == 0) { redmn[wid] = lmn; redmx[wid] = lmx; }
        __syncthreads();
        if (wid == 0) {
            float a = (lane < nt / 32) ? redmn[lane] : 3.4e38f;
            float c = (lane < nt / 32) ? redmx[lane] : -3.4e38f;
            a = wredmin(a);
            c = wredmax(c);
            if (lane == 0) { s_mn = a; s_mx = c; }
        }
        __syncthreads();
        const float mn = s_mn, mx = s_mx;
        for (int j = tid; j < nl; j += nt)
            cur[j] = (cur[j] - mn) / (mx - mn + 1e-8f);
        __syncthreads();
        len = nl;
    }

    const float sc = ps[it], bi = pb[it];
    for (int s = tid; s < SEQ; s += nt) {
        double x = (double)s / (double)(SEQ - 1);
        double t = x * (double)(len - 1);
        int i0 = (int)t;
        if (i0 > len - 2) i0 = len - 2;
        double fr = t - (double)i0;
        float w = (float)((1.0 - fr) * (double)cur[i0] + fr * (double)cur[i0 + 1]);
        float z = fmaf(w, sc, bi);
        g_w[s] = fmaxf(z, 0.0f) + log1pf(expf(-fabsf(z)));
    }

    if (tid == 0) {
        float acc = b2[0];
        for (int j = 0; j < 64; ++j) {
            float h = w1[it * 64 + j] + b1[j];
            if (h > 0.0f) acc = fmaf(h, w2[j], acc);
        }
        g_blend = 1.0f / (1.0f + expf(-acc));
    }
}

// ---------------- column mean of V per batch -----------------------------------
__global__ void meanv_kernel(const float* __restrict__ V) {
    const int b = blockIdx.y;
    const int d = (blockIdx.x << 7) + threadIdx.x;
    const float* p = V + (size_t)b * SEQ * DIM + d;
    float a0 = 0.f, a1 = 0.f, a2 = 0.f, a3 = 0.f;
    #pragma unroll 4
    for (int k = 0; k < SEQ; k += 4) {
        a0 += p[(size_t)(k + 0) * DIM];
        a1 += p[(size_t)(k + 1) * DIM];
        a2 += p[(size_t)(k + 2) * DIM];
        a3 += p[(size_t)(k + 3) * DIM];
    }
    g_meanV[b * DIM + d] = (a0 + a1 + a2 + a3) * (1.0f / SEQ);
}

// ---------------- split Q (fp16 hi/lo) and K (fp16 single) -----------------------
__global__ __launch_bounds__(256) void splitqk_kernel(const float* __restrict__ Q,
                                                      const float* __restrict__ K) {
    const size_t i = (size_t)blockIdx.x * 256 + threadIdx.x;
    if (blockIdx.y == 0) {
        float4 v = ((const float4*)Q)[i];
        __half h0 = __float2half_rn(v.x), h1 = __float2half_rn(v.y);
        __half h2 = __float2half_rn(v.z), h3 = __float2half_rn(v.w);
        __half2 hh[2] = {__halves2half2(h0, h1), __halves2half2(h2, h3)};
        __half2 ll[2] = {
            __floats2half2_rn(v.x - __half2float(h0), v.y - __half2float(h1)),
            __floats2half2_rn(v.z - __half2float(h2), v.w - __half2float(h3))};
        ((uint2*)g_qhi)[i] = *(uint2*)hh;
        ((uint2*)g_qlo)[i] = *(uint2*)ll;
    } else {
        float4 v = ((const float4*)K)[i];
        __half2 kk[2] = {__floats2half2_rn(v.x, v.y), __floats2half2_rn(v.z, v.w)};
        ((uint2*)g_k16)[i] = *(uint2*)kk;
    }
}

// ---------------- transpose V: Vt[b][d][s] fp16 single ---------------------------
__global__ void splitv_kernel(const float* __restrict__ V) {
    __shared__ float t[32][33];
    const int b = blockIdx.z;
    const int s0 = blockIdx.x << 5, d0 = blockIdx.y << 5;
    const int tx = threadIdx.x, ty = threadIdx.y;
    const float* src = V + ((size_t)b * SEQ + s0) * DIM + d0 + tx;
    #pragma unroll
    for (int i = 0; i < 32; i += 8) t[ty + i][tx] = src[(size_t)(ty + i) * DIM];
    __syncthreads();
    #pragma unroll
    for (int i = 0; i < 32; i += 8) {
        float x = t[tx][ty + i];
        size_t o = ((size_t)b * DIM + d0 + ty + i) * SEQ + s0 + tx;
        g_vt16[o] = __float2half_rn(x);
    }
}

#define TILE_B   8192u               // bytes per 128x32 16-bit tile
#define TILE64_B 16384u              // bytes per 128x64 16-bit tile

// =================================================================================
// Scores GEMM core: 2-term fp16, K-chunk 64, 128B swizzled rows (c ^= row&7).
// 256 threads, 2x4 warp grid, warp tile 64x32.
// Stage = [Ahi, Alo, K] = 48 KB; 2 stages (96 KB); one barrier per 64-K chunk.
// =================================================================================
#define SC_STAGE_B (3u * TILE64_B)      // 49152
#define SC_DSMEM   (2u * SC_STAGE_B)    // 98304

#define SC_ISSUE_CHUNK(bufbase, kb) do { \
    _Pragma("unroll") \
    for (int i = 0; i < 4; ++i) { \
        CP_ASYNC16((bufbase) + 0u * TILE64_B + st[i], aHi + ga[i] + (kb)); \
        CP_ASYNC16((bufbase) + 1u * TILE64_B + st[i], aLo + ga[i] + (kb)); \
        CP_ASYNC16((bufbase) + 2u * TILE64_B + st[i], bK + gb[i] + (kb)); \
    } \
    CP_COMMIT(); \
} while (0)

template <int LDA, int LDB, int CPS>   // CPS = number of 64-K chunks
__device__ __forceinline__ void scores_mainloop(
    const __half* aHi, const __half* aLo, const __half* bK,
    __half* smem, float c[4][4][4])
{
    const int tid = threadIdx.x;
    const int wid = tid >> 5, lane = tid & 31;
    const int wm = wid & 1, wn = wid >> 1;

    const uint32_t smem_base = smem_u32(smem);

    uint32_t st[4];
    size_t ga[4], gb[4];
    #pragma unroll
    for (int i = 0; i < 4; ++i) {
        const int idx = i * 256 + tid;
        const int r = idx >> 3, cc = idx & 7;
        st[i] = (uint32_t)(r * 128 + ((cc ^ (r & 7)) << 4));
        ga[i] = (size_t)r * LDA + cc * 8;
        gb[i] = (size_t)r * LDB + cc * 8;
    }

    const int a_row = wm * 64 + (lane & 15);
    const int a_hi  = (lane >> 4) & 1;
    const int xa    = a_row & 7;
    const uint32_t a_base = (uint32_t)(a_row * 128);
    const int b_row = wn * 32 + (lane & 7) + ((lane & 16) ? 8 : 0);
    const int b_hi  = (lane >> 3) & 1;
    const int xb    = b_row & 7;
    const uint32_t b_base = (uint32_t)(b_row * 128);

    SC_ISSUE_CHUNK(smem_base, 0);

    #pragma unroll 1
    for (int ch = 0; ch < CPS; ++ch) {
        CP_WAIT(0);
        __syncthreads();
        if (ch + 1 < CPS) {
            const uint32_t nb = smem_base + (uint32_t)((ch + 1) & 1) * SC_STAGE_B;
            SC_ISSUE_CHUNK(nb, (ch + 1) * 64);
        }

        const uint32_t bb = smem_base + (uint32_t)(ch & 1) * SC_STAGE_B;
        #pragma unroll
        for (int ks = 0; ks < 4; ++ks) {
            const uint32_t ka  = (uint32_t)(((ks * 2 + a_hi) ^ xa) << 4);
            const uint32_t kb2 = (uint32_t)(((ks * 2 + b_hi) ^ xb) << 4);
            uint32_t ah[4][4], bh[2][4];
            #pragma unroll
            for (int mt = 0; mt < 4; ++mt)
                ldsm_x4(ah[mt], bb + 0u * TILE64_B + a_base + mt * 2048u + ka);
            #pragma unroll
            for (int ntp = 0; ntp < 2; ++ntp)
                ldsm_x4(bh[ntp], bb + 2u * TILE64_B + b_base + ntp * 2048u + kb2);
            #pragma unroll
            for (int mt = 0; mt < 4; ++mt)
                #pragma unroll
                for (int nt = 0; nt < 4; ++nt)
                    hmma16816f(c[mt][nt], ah[mt], &bh[nt >> 1][(nt & 1) * 2]);
            {
                uint32_t al[4][4];
                #pragma unroll
                for (int mt = 0; mt < 4; ++mt)
                    ldsm_x4(al[mt], bb + 1u * TILE64_B + a_base + mt * 2048u + ka);
                #pragma unroll
                for (int mt = 0; mt < 4; ++mt)
                    #pragma unroll
                    for (int nt = 0; nt < 4; ++nt)
                        hmma16816f(c[mt][nt], al[mt], &bh[nt >> 1][(nt & 1) * 2]);
            }
        }
    }
}

// ---------------- GEMM1: U = exp((Q.K^T) * w[n]/sqrt(D)) -> fp16 + row partials ---
__global__ __launch_bounds__(256, 2) void scores_mma_kernel() {
    extern __shared__ __half dynsmem_h[];
    __shared__ float s_ws[128];
    __shared__ float s_rs[4][128];   // per-wn partial row sums

    const int tid = threadIdx.x, wid = tid >> 5, lane = tid & 31;
    const int grp = lane >> 2, t4 = lane & 3;
    const int wm = wid & 1, wn = wid >> 1;
    const int b = blockIdx.z, m0 = blockIdx.y << 7, n0 = blockIdx.x << 7;

    if (tid < 128) s_ws[tid] = g_w[n0 + tid] * 0.04419417382415922f;

    const size_t boff = (size_t)b * SEQ * DIM;
    const __half* A0 = g_qhi + boff + (size_t)m0 * DIM;
    const __half* A1 = g_qlo + boff + (size_t)m0 * DIM;
    const __half* B0 = g_k16 + boff + (size_t)n0 * DIM;

    float c[4][4][4];
    #pragma unroll
    for (int i = 0; i < 4; ++i)
        #pragma unroll
        for (int j = 0; j < 4; ++j)
            #pragma unroll
            for (int q = 0; q < 4; ++q) c[i][j][q] = 0.f;

    scores_mainloop<DIM, DIM, DIM / 64>(A0, A1, B0, dynsmem_h, c);

    __half* sb = g_sp16 + (size_t)b * SEQ * SEQ;
    float rsum[4][2];   // per (mt, rr) row partial over this thread's 8 cols
    #pragma unroll
    for (int mt = 0; mt < 4; ++mt) { rsum[mt][0] = 0.f; rsum[mt][1] = 0.f; }

    #pragma unroll
    for (int mt = 0; mt < 4; ++mt) {
        #pragma unroll
        for (int nt = 0; nt < 4; ++nt) {
            const int col_l = wn * 32 + nt * 8 + t4 * 2;
            const int col = n0 + col_l;
            const float w0 = s_ws[col_l], w1v = s_ws[col_l + 1];
            #pragma unroll
            for (int rr = 0; rr < 2; ++rr) {
                const int row = m0 + wm * 64 + mt * 16 + grp + rr * 8;
                float u0 = __expf(c[mt][nt][2 * rr]     * w0);
                float u1 = __expf(c[mt][nt][2 * rr + 1] * w1v);
                rsum[mt][rr] += u0 + u1;
                __half2 o = __floats2half2_rn(u0, u1);
                *(__half2*)(sb + (size_t)row * SEQ + col) = o;
            }
        }
    }

    // reduce row partials over t4 (lanes xor 1, 2)
    #pragma unroll
    for (int mt = 0; mt < 4; ++mt)
        #pragma unroll
        for (int rr = 0; rr < 2; ++rr) {
            float v = rsum[mt][rr];
            v += __shfl_xor_sync(0xffffffffu, v, 1);
            v += __shfl_xor_sync(0xffffffffu, v, 2);
            rsum[mt][rr] = v;
        }
    if (t4 == 0) {
        #pragma unroll
        for (int mt = 0; mt < 4; ++mt)
            #pragma unroll
            for (int rr = 0; rr < 2; ++rr)
                s_rs[wn][wm * 64 + mt * 16 + grp + rr * 8] = rsum[mt][rr];
    }
    __syncthreads();
    if (tid < 128) {
        float v = s_rs[0][tid] + s_rs[1][tid] + s_rs[2][tid] + s_rs[3][tid];
        g_rowpart[blockIdx.x][(size_t)b * SEQ + m0 + tid] = v;
    }
}

// ---------------- rowsum: 1/Z per row (deterministic fold of 16 partials) --------
__global__ __launch_bounds__(256) void rowsum_kernel() {
    const size_t r = (size_t)blockIdx.x * 256 + threadIdx.x;
    float s = 0.f;
    #pragma unroll
    for (int j = 0; j < 16; ++j) s += g_rowpart[j][r];
    g_rowinv[r] = 1.0f / s;
}

// =================================================================================
// PV GEMM core: 1-term fp16, K-chunk 64 (two 32-sub-tiles per stage).
// Stage = [A_k0, A_k1, B_k0, B_k1] = 32 KB; 3 stages. Full K = 2048 (no split).
// =================================================================================
#define PV_STAGE_B (4u * TILE_B)        // 32768
#define PV_DSMEM   (3u * PV_STAGE_B)    // 98304

#define PV_ISSUE_CHUNK(bufbase, kb) do { \
    CP_ASYNC16((bufbase) + 0u * TILE_B + st0, aP + g0a + (kb)); \
    CP_ASYNC16((bufbase) + 0u * TILE_B + st1, aP + g1a + (kb)); \
    CP_ASYNC16((bufbase) + 1u * TILE_B + st0, aP + g0a + (kb) + 32); \
    CP_ASYNC16((bufbase) + 1u * TILE_B + st1, aP + g1a + (kb) + 32); \
    CP_ASYNC16((bufbase) + 2u * TILE_B + st0, bV + g0b + (kb)); \
    CP_ASYNC16((bufbase) + 2u * TILE_B + st1, bV + g1b + (kb)); \
    CP_ASYNC16((bufbase) + 3u * TILE_B + st0, bV + g0b + (kb) + 32); \
    CP_ASYNC16((bufbase) + 3u * TILE_B + st1, bV + g1b + (kb) + 32); \
    CP_COMMIT(); \
} while (0)

template <int LDA, int LDB, int CPS>   // CPS = number of 64-K chunks
__device__ __forceinline__ void pv_mainloop(
    const __half* aP, const __half* bV,
    __half* smem, float c[4][4][4])
{
    const int tid = threadIdx.x;
    const int wid = tid >> 5, lane = tid & 31;
    const int wm = wid & 1, wn = wid >> 1;

    const uint32_t smem_base = smem_u32(smem);

    const int r0 = tid >> 2,         c0 = tid & 3;
    const int r1 = (256 + tid) >> 2, c1 = tid & 3;
    const uint32_t st0 = (uint32_t)(r0 * 64 + ((c0 ^ ((r0 >> 1) & 3)) << 4));
    const uint32_t st1 = (uint32_t)(r1 * 64 + ((c1 ^ ((r1 >> 1) & 3)) << 4));
    const size_t g0a = (size_t)r0 * LDA + c0 * 8, g1a = (size_t)r1 * LDA + c1 * 8;
    const size_t g0b = (size_t)r0 * LDB + c0 * 8, g1b = (size_t)r1 * LDB + c1 * 8;

    const int a_row = wm * 64 + (lane & 15);
    const int a_hi  = (lane >> 4) & 1;
    const int xa    = (a_row >> 1) & 3;
    const uint32_t a_base = (uint32_t)(a_row * 64);
    const int b_row = wn * 32 + (lane & 7) + ((lane & 16) ? 8 : 0);
    const int b_hi  = (lane >> 3) & 1;
    const int xb    = (b_row >> 1) & 3;
    const uint32_t b_base = (uint32_t)(b_row * 64);

    PV_ISSUE_CHUNK(smem_base, 0);
    PV_ISSUE_CHUNK(smem_base + PV_STAGE_B, 64);

    #pragma unroll 1
    for (int ch = 0; ch < CPS; ++ch) {
        if (ch + 1 < CPS) { CP_WAIT(1); } else { CP_WAIT(0); }
        __syncthreads();
        if (ch + 2 < CPS) {
            const uint32_t nb = smem_base + (uint32_t)((ch + 2) % 3) * PV_STAGE_B;
            const int kb = (ch + 2) * 64;
            PV_ISSUE_CHUNK(nb, kb);
        }

        const uint32_t bb = smem_base + (uint32_t)(ch % 3) * PV_STAGE_B;
        #pragma unroll
        for (int sub = 0; sub < 2; ++sub) {
            #pragma unroll
            for (int ks = 0; ks < 2; ++ks) {
                const uint32_t ka  = (uint32_t)(((ks * 2 + a_hi) ^ xa) << 4);
                const uint32_t kb2 = (uint32_t)(((ks * 2 + b_hi) ^ xb) << 4);
                uint32_t ah[4][4], bh[2][4];
                #pragma unroll
                for (int mt = 0; mt < 4; ++mt)
                    ldsm_x4(ah[mt], bb + (uint32_t)sub * TILE_B + a_base + mt * 1024u + ka);
                #pragma unroll
                for (int ntp = 0; ntp < 2; ++ntp)
                    ldsm_x4(bh[ntp], bb + (2u + sub) * TILE_B + b_base + ntp * 1024u + kb2);
                #pragma unroll
                for (int mt = 0; mt < 4; ++mt)
                    #pragma unroll
                    for (int nt = 0; nt < 4; ++nt)
                        hmma16816f(c[mt][nt], ah[mt], &bh[nt >> 1][(nt & 1) * 2]);
            }
        }
    }
}

// ---------------- GEMM2: out = blend/Z * (U.V) + (1-blend) * meanV ---------------
__global__ __launch_bounds__(256, 2) void pv_mma_kernel(float* __restrict__ out) {
    extern __shared__ __half dynsmem_h[];
    __shared__ float s_mv[128];
    __shared__ float s_bl;

    const int tid = threadIdx.x, wid = tid >> 5, lane = tid & 31;
    const int grp = lane >> 2, t4 = lane & 3;
    const int wm = wid & 1, wn = wid >> 1;
    const int b = blockIdx.z;
    const int m0 = blockIdx.y << 7, n0 = blockIdx.x << 7;

    if (tid == 0) s_bl = g_blend;
    __syncthreads();
    const float blend = s_bl;
    if (tid < 128) s_mv[tid] = (1.0f - blend) * g_meanV[b * DIM + n0 + tid];

    const __half* A0 = g_sp16 + (size_t)b * SEQ * SEQ + (size_t)m0 * SEQ;
    const __half* B0 = g_vt16 + (size_t)b * DIM * SEQ + (size_t)n0 * SEQ;

    float c[4][4][4];
    #pragma unroll
    for (int i = 0; i < 4; ++i)
        #pragma unroll
        for (int j = 0; j < 4; ++j)
            #pragma unroll
            for (int q = 0; q < 4; ++q) c[i][j][q] = 0.f;

    pv_mainloop<SEQ, SEQ, SEQ / 64>(A0, B0, dynsmem_h, c);

    #pragma unroll
    for (int mt = 0; mt < 4; ++mt) {
        #pragma unroll
        for (int rr = 0; rr < 2; ++rr) {
            const int row = m0 + wm * 64 + mt * 16 + grp + rr * 8;
            const float sc = blend * g_rowinv[(size_t)b * SEQ + row];
            #pragma unroll
            for (int nt = 0; nt < 4; ++nt) {
                const int col_l = wn * 32 + nt * 8 + t4 * 2;
                const int col = n0 + col_l;
                float2 o;
                o.x = fmaf(sc, c[mt][nt][2 * rr],     s_mv[col_l]);
                o.y = fmaf(sc, c[mt][nt][2 * rr + 1], s_mv[col_l + 1]);
                *(float2*)(out + ((size_t)b * SEQ + row) * DIM + col) = o;
            }
        }
    }
}

// ---------------- launch -----------------------------------------------------------
extern "C" void kernel_launch(void* const* d_in, const int* in_sizes, int n_in,
                              void* d_out, int out_size) {
    const float* q  = (const float*)d_in[0];
    const float* k  = (const float*)d_in[1];
    const float* v  = (const float*)d_in[2];
    const float* ps = (const float*)d_in[3];
    const float* pb = (const float*)d_in[4];
    const float* w1 = (const float*)d_in[5];
    const float* b1 = (const float*)d_in[6];
    const float* w2 = (const float*)d_in[7];
    const float* b2 = (const float*)d_in[8];
    float* out = (float*)d_out;

    static bool init_done = false;
    static cudaStream_t s_aux;
    static cudaEvent_t ev_fork, ev_prep, ev_aux;
    if (!init_done) {
        cudaFuncSetAttribute(scores_mma_kernel,
                             cudaFuncAttributeMaxDynamicSharedMemorySize, SC_DSMEM);
        cudaFuncSetAttribute(pv_mma_kernel,
                             cudaFuncAttributeMaxDynamicSharedMemorySize, PV_DSMEM);
        cudaStreamCreateWithFlags(&s_aux, cudaStreamNonBlocking);
        cudaEventCreateWithFlags(&ev_fork, cudaEventDisableTiming);
        cudaEventCreateWithFlags(&ev_prep, cudaEventDisableTiming);
        cudaEventCreateWithFlags(&ev_aux, cudaEventDisableTiming);
        init_done = true;
    }

    // Fork: aux stream handles prep / splitv / meanv concurrently with splitqk.
    cudaEventRecord(ev_fork, 0);
    cudaStreamWaitEvent(s_aux, ev_fork, 0);
    prep_kernel<<<1, 1024, 0, s_aux>>>(ps, pb, w1, b1, w2, b2);
    cudaEventRecord(ev_prep, s_aux);
    splitv_kernel<<<dim3(SEQ / 32, DIM / 32, BATCH), dim3(32, 8), 0, s_aux>>>(v);
    meanv_kernel<<<dim3(DIM / 128, BATCH), 128, 0, s_aux>>>(v);
    cudaEventRecord(ev_aux, s_aux);

    // Main stream
    splitqk_kernel<<<dim3((BATCH * SEQ * DIM / 4) / 256, 2), 256>>>(q, k);
    cudaStreamWaitEvent(0, ev_prep, 0);   // scores epilogue needs g_w
    scores_mma_kernel<<<dim3(SEQ / 128, SEQ / 128, BATCH), 256, SC_DSMEM>>>();
    rowsum_kernel<<<(BATCH * SEQ) / 256, 256>>>();
    cudaStreamWaitEvent(0, ev_aux, 0);    // pv needs g_vt16, g_meanV, g_blend
    pv_mma_kernel<<<dim3(DIM / 128, SEQ / 128, BATCH), 256, PV_DSMEM>>>(out);
}